// round 7
// baseline (speedup 1.0000x reference)
#include <cuda_runtime.h>
#include <cuda_bf16.h>
#include <math.h>
#include <stdint.h>

// ---------------- problem constants ----------------
#define BB 2
#define LL 4096
#define DM 256
#define DIN 1024          // D_INNER
#define GN_ 128           // NGROUPS*D_STATE
#define HH 8              // NHEADS
#define PP 128            // HEADDIM
#define DPROJ 2312        // D_IN_PROJ (logical)
#define DPROJP 2560       // padded to 10*256
#define DCONVCH 1280      // D_INNER + 2*GN
#define ROWS (BB*LL)      // 8192
#define EPS_ 1e-5f

#define NPART 8
#define NPN 16            // n per partition
#define SS 8              // scan superstep (timesteps per pipeline stage)
#define DST 4             // pipeline depth (stages)
#define NSUP (LL / SS)    // 512

// ---------------- scratch (static device allocations) ----------------
__device__ __align__(16) __nv_bfloat16 g_xh[(size_t)ROWS * DM];
__device__ __align__(16) __nv_bfloat16 g_xl[(size_t)ROWS * DM];
__device__ __align__(16) __nv_bfloat16 g_WinT_h[(size_t)DPROJP * DM];
__device__ __align__(16) __nv_bfloat16 g_WinT_l[(size_t)DPROJP * DM];
__device__ __align__(16) __nv_bfloat16 g_WoutT_h[(size_t)DM * DIN];
__device__ __align__(16) __nv_bfloat16 g_WoutT_l[(size_t)DM * DIN];
__device__ __align__(16) __nv_bfloat16 g_yh[(size_t)ROWS * DIN];
__device__ __align__(16) __nv_bfloat16 g_yl[(size_t)ROWS * DIN];
__device__ float g_zx[(size_t)ROWS * DPROJP];
__device__ float g_xconv[(size_t)ROWS * DCONVCH];
__device__ float g_dA[(size_t)ROWS * HH];
__device__ float g_xsh[(size_t)ROWS * PP];
__device__ float g_bh[(size_t)ROWS * HH * GN_];    // B*bscale*dt (33.5 MB)
__device__ float g_ypart[(size_t)NPART * ROWS * DIN];

// ---------------- small helpers ----------------
__device__ __forceinline__ float siluf(float x) { return x / (1.f + expf(-x)); }

__device__ __forceinline__ void split_bf16(float v, __nv_bfloat16& h, __nv_bfloat16& l) {
    h = __float2bfloat16(v);
    l = __float2bfloat16(v - __bfloat162float(h));
}

typedef unsigned long long ull;
__device__ __forceinline__ ull f32x2_fma(ull a, ull b, ull c) {
    ull d; asm("fma.rn.f32x2 %0, %1, %2, %3;" : "=l"(d) : "l"(a), "l"(b), "l"(c)); return d;
}
__device__ __forceinline__ ull f32x2_mul(ull a, ull b) {
    ull d; asm("mul.rn.f32x2 %0, %1, %2;" : "=l"(d) : "l"(a), "l"(b)); return d;
}
__device__ __forceinline__ ull f32x2_pack(float lo, float hi) {
    ull d; asm("mov.b64 %0, {%1, %2};" : "=l"(d) : "f"(lo), "f"(hi)); return d;
}
__device__ __forceinline__ float2 f32x2_unpack(ull v) {
    float2 r; asm("mov.b64 {%0, %1}, %2;" : "=f"(r.x), "=f"(r.y) : "l"(v)); return r;
}

__device__ __forceinline__ uint32_t smem_u32(const void* p) {
    uint32_t a;
    asm("{ .reg .u64 t; cvta.to.shared.u64 t, %1; cvt.u32.u64 %0, t; }" : "=r"(a) : "l"(p));
    return a;
}

// ---------------- async copy helpers ----------------
__device__ __forceinline__ void cp_async16(uint32_t saddr, const void* gptr) {
    asm volatile("cp.async.cg.shared.global [%0], [%1], 16;"
                 :: "r"(saddr), "l"(gptr) : "memory");
}
__device__ __forceinline__ void cp_async4(uint32_t saddr, const void* gptr) {
    asm volatile("cp.async.ca.shared.global [%0], [%1], 4;"
                 :: "r"(saddr), "l"(gptr) : "memory");
}
#define CP_COMMIT() asm volatile("cp.async.commit_group;" ::: "memory")
template <int N> __device__ __forceinline__ void cp_wait() {
    asm volatile("cp.async.wait_group %0;" :: "n"(N) : "memory");
}

__device__ __forceinline__ void ldmatrix_x4(uint32_t* r, uint32_t addr) {
    asm volatile("ldmatrix.sync.aligned.m8n8.x4.shared.b16 {%0,%1,%2,%3}, [%4];"
                 : "=r"(r[0]), "=r"(r[1]), "=r"(r[2]), "=r"(r[3]) : "r"(addr));
}

__device__ __forceinline__ void mma_bf16(float* c, const uint32_t* a, uint32_t b0, uint32_t b1) {
    asm volatile(
        "mma.sync.aligned.m16n8k16.row.col.f32.bf16.bf16.f32 "
        "{%0,%1,%2,%3}, {%4,%5,%6,%7}, {%8,%9}, {%0,%1,%2,%3};"
        : "+f"(c[0]), "+f"(c[1]), "+f"(c[2]), "+f"(c[3])
        : "r"(a[0]), "r"(a[1]), "r"(a[2]), "r"(a[3]), "r"(b0), "r"(b1));
}

// ---------------- 1) LayerNorm -> split bf16 (single-pass, shuffle) ----------------
__global__ void ln_kernel(const float* __restrict__ u,
                          const float* __restrict__ gamma,
                          const float* __restrict__ beta) {
    __shared__ float w1[8], w2[8], bc[2];
    const int row = blockIdx.x, tid = threadIdx.x;
    const int wid = tid >> 5, lane = tid & 31;
    float v = u[(size_t)row * DM + tid];
    float s1 = v, s2 = v * v;
    #pragma unroll
    for (int o = 16; o > 0; o >>= 1) {
        s1 += __shfl_xor_sync(0xffffffffu, s1, o);
        s2 += __shfl_xor_sync(0xffffffffu, s2, o);
    }
    if (lane == 0) { w1[wid] = s1; w2[wid] = s2; }
    __syncthreads();
    if (wid == 0) {
        float a = (lane < 8) ? w1[lane] : 0.f;
        float b = (lane < 8) ? w2[lane] : 0.f;
        #pragma unroll
        for (int o = 4; o > 0; o >>= 1) {
            a += __shfl_xor_sync(0xffffffffu, a, o);
            b += __shfl_xor_sync(0xffffffffu, b, o);
        }
        if (lane == 0) {
            float mu = a * (1.f / 256.f);
            float var = b * (1.f / 256.f) - mu * mu;
            bc[0] = mu;
            bc[1] = rsqrtf(var + EPS_);
        }
    }
    __syncthreads();
    float xn = (v - bc[0]) * bc[1] * gamma[tid] + beta[tid];
    __nv_bfloat16 h, l;
    split_bf16(xn, h, l);
    g_xh[(size_t)row * DM + tid] = h;
    g_xl[(size_t)row * DM + tid] = l;
}

// ---------------- transposes + split of weights (tiled, coalesced) ----------------
__global__ void transpose_win_kernel(const float* __restrict__ W_in) {
    __shared__ float tile[32][33];
    const int tx = threadIdx.x, ty = threadIdx.y;        // 32 x 8
    const int n0 = blockIdx.x * 32, k0 = blockIdx.y * 32;
    #pragma unroll
    for (int dy = 0; dy < 32; dy += 8) {
        const int n = n0 + tx, k = k0 + ty + dy;
        tile[ty + dy][tx] = (n < DPROJ) ? W_in[(size_t)k * DPROJ + n] : 0.f;
    }
    __syncthreads();
    #pragma unroll
    for (int dy = 0; dy < 32; dy += 8) {
        const int n = n0 + ty + dy, k = k0 + tx;
        float v = tile[tx][ty + dy];
        __nv_bfloat16 h, l;
        split_bf16(v, h, l);
        g_WinT_h[(size_t)n * DM + k] = h;
        g_WinT_l[(size_t)n * DM + k] = l;
    }
}

__global__ void transpose_wout_kernel(const float* __restrict__ W_out) {
    __shared__ float tile[32][33];
    const int tx = threadIdx.x, ty = threadIdx.y;        // 32 x 8
    const int n0 = blockIdx.x * 32, k0 = blockIdx.y * 32;
    #pragma unroll
    for (int dy = 0; dy < 32; dy += 8) {
        tile[ty + dy][tx] = W_out[(size_t)(k0 + ty + dy) * DM + n0 + tx];
    }
    __syncthreads();
    #pragma unroll
    for (int dy = 0; dy < 32; dy += 8) {
        const int n = n0 + ty + dy, k = k0 + tx;
        float v = tile[tx][ty + dy];
        __nv_bfloat16 h, l;
        split_bf16(v, h, l);
        g_WoutT_h[(size_t)n * DIN + k] = h;
        g_WoutT_l[(size_t)n * DIN + k] = l;
    }
}

// ---------------- 2) split-bf16 GEMM on mma.sync, 128x256 tile, 3-stage ----------------
#define STR 40                         // smem row stride (bf16)
#define ASTG (128 * STR * 2)           // A stage bytes (10240)
#define BSTG (256 * STR * 2)           // B stage bytes (20480)
#define STAGE (ASTG + BSTG)            // 30720
#define GEMM_SMEM (3 * STAGE)          // 92160

__global__ void __launch_bounds__(256, 1)
mma_gemm_kernel(const __nv_bfloat16* __restrict__ Ah,
                const __nv_bfloat16* __restrict__ Al,
                const __nv_bfloat16* __restrict__ Bh,
                const __nv_bfloat16* __restrict__ Bl,
                int Kin,
                float* __restrict__ C, int ldc,
                const float* __restrict__ Cadd) {
    extern __shared__ char dsmem[];
    const uint32_t sbase = smem_u32(dsmem);

    const int tid = threadIdx.x;
    const int wid = tid >> 5, lid = tid & 31;
    const int wm = wid >> 2;           // 0..1  (M 64)
    const int wn = wid & 3;            // 0..3  (N 64)
    const int tileRow = blockIdx.y * 128;
    const int tileCol = blockIdx.x * 256;

    // A staging: thread -> (row = tid/2, half = (tid&1)*16 elems), 32B each
    const int aRow = tid >> 1;
    const int aSeg = (tid & 1) * 16;
    const uint32_t aOffB = (uint32_t)(aRow * STR + aSeg) * 2;
    // B staging: thread -> full row tid, 64B (4x16B)
    const uint32_t bOffB = (uint32_t)(tid * STR) * 2;

    const int aRowOff = (lid & 7) + ((lid >> 3) & 1) * 8;
    const int aKOff   = (lid >> 4) * 8;
    const int bNOff   = (lid & 7) + ((lid >> 4) & 1) * 8;
    const int bKOff   = ((lid >> 3) & 1) * 8;

    float acc[4][8][4];
    #pragma unroll
    for (int i = 0; i < 4; ++i)
        #pragma unroll
        for (int j = 0; j < 8; ++j)
            #pragma unroll
            for (int q = 0; q < 4; ++q) acc[i][j][q] = 0.f;

    const int cps = Kin / 32;
    const int T = 3 * cps;

    auto issue = [&](int c) {
        if (c < T) {
            const int seg = c / cps;
            const int kc = c - seg * cps;
            const __nv_bfloat16* Ag = (seg == 1) ? Al : Ah;
            const __nv_bfloat16* Bg = (seg == 2) ? Bl : Bh;
            const __nv_bfloat16* ga = Ag + (size_t)(tileRow + aRow) * Kin + kc * 32 + aSeg;
            const __nv_bfloat16* gb = Bg + (size_t)(tileCol + tid) * Kin + kc * 32;
            const int buf = c % 3;
            const uint32_t sa = sbase + (uint32_t)buf * STAGE + aOffB;
            const uint32_t sb = sbase + (uint32_t)buf * STAGE + ASTG + bOffB;
            cp_async16(sa, ga);
            cp_async16(sa + 16, ga + 8);
            cp_async16(sb,      gb);
            cp_async16(sb + 16, gb + 8);
            cp_async16(sb + 32, gb + 16);
            cp_async16(sb + 48, gb + 24);
        }
        CP_COMMIT();
    };

    issue(0); issue(1);
    for (int c = 0; c < T; ++c) {
        cp_wait<1>();
        __syncthreads();

        const int buf = c % 3;
        const uint32_t aB = sbase + (uint32_t)buf * STAGE;
        const uint32_t bB = aB + ASTG;
        #pragma unroll
        for (int kk = 0; kk < 32; kk += 16) {
            uint32_t afr[4][4];
            #pragma unroll
            for (int mt = 0; mt < 4; ++mt) {
                uint32_t addr = aB + (uint32_t)((wm * 64 + mt * 16 + aRowOff) * STR + kk + aKOff) * 2;
                ldmatrix_x4(afr[mt], addr);
            }
            uint32_t bfr[4][4];
            #pragma unroll
            for (int pr = 0; pr < 4; ++pr) {
                uint32_t addr = bB + (uint32_t)((wn * 64 + pr * 16 + bNOff) * STR + kk + bKOff) * 2;
                ldmatrix_x4(bfr[pr], addr);
            }
            #pragma unroll
            for (int mt = 0; mt < 4; ++mt)
                #pragma unroll
                for (int nt = 0; nt < 8; ++nt) {
                    const uint32_t* bp = bfr[nt >> 1];
                    const int hi = (nt & 1) * 2;
                    mma_bf16(acc[mt][nt], afr[mt], bp[hi], bp[hi + 1]);
                }
        }
        issue(c + 2);
    }

    const int gID = lid >> 2, qid = lid & 3;
    #pragma unroll
    for (int mt = 0; mt < 4; ++mt) {
        const int r0 = tileRow + wm * 64 + mt * 16 + gID;
        #pragma unroll
        for (int nt = 0; nt < 8; ++nt) {
            const int col = tileCol + wn * 64 + nt * 8 + qid * 2;
            float2 v0 = make_float2(acc[mt][nt][0], acc[mt][nt][1]);
            float2 v1 = make_float2(acc[mt][nt][2], acc[mt][nt][3]);
            if (Cadd) {
                const float2 a0 = *(const float2*)(Cadd + (size_t)r0 * ldc + col);
                const float2 a1 = *(const float2*)(Cadd + (size_t)(r0 + 8) * ldc + col);
                v0.x += a0.x; v0.y += a0.y;
                v1.x += a1.x; v1.y += a1.y;
            }
            *(float2*)(C + (size_t)r0 * ldc + col) = v0;
            *(float2*)(C + (size_t)(r0 + 8) * ldc + col) = v1;
        }
    }
}

// ---------------- 3) causal depthwise conv (K=4) + SiLU, register ring over l ----------------
#define CLT 16
__global__ void conv_kernel(const float* __restrict__ conv_w,
                            const float* __restrict__ conv_b) {
    const int c = blockIdx.x * 256 + threadIdx.x;   // 0..1279 (grid.x = 5)
    const int l0 = blockIdx.y * CLT;
    const int b = blockIdx.z;
    const size_t base = ((size_t)b * LL) * DPROJP + DIN + c;
    const float w0 = conv_w[c * 4 + 0], w1 = conv_w[c * 4 + 1];
    const float w2 = conv_w[c * 4 + 2], w3 = conv_w[c * 4 + 3];
    const float bias = conv_b[c];

    float x0 = 0.f, x1 = 0.f, x2 = 0.f;
    if (l0 > 0) {
        x0 = g_zx[base + (size_t)(l0 - 3) * DPROJP];
        x1 = g_zx[base + (size_t)(l0 - 2) * DPROJP];
        x2 = g_zx[base + (size_t)(l0 - 1) * DPROJP];
    }
    #pragma unroll
    for (int i = 0; i < CLT; ++i) {
        const float x3 = g_zx[base + (size_t)(l0 + i) * DPROJP];
        float acc = fmaf(x0, w0, bias);
        acc = fmaf(x1, w1, acc);
        acc = fmaf(x2, w2, acc);
        acc = fmaf(x3, w3, acc);
        g_xconv[((size_t)b * LL + l0 + i) * DCONVCH + c] = siluf(acc);
        x0 = x1; x1 = x2; x2 = x3;
    }
}

// ---------------- 4) prep: dt/dA + x_shared mean + prescaled B (fused) ----------------
__global__ void prep_kernel(const float* __restrict__ Bscale,
                            const float* __restrict__ dt_bias,
                            const float* __restrict__ A_log) {
    __shared__ float sdt[HH];
    const int row = blockIdx.x, p = threadIdx.x;    // 128 threads
    if (p < HH) {
        float dt = g_zx[(size_t)row * DPROJP + 2304 + p] + dt_bias[p];
        float dtp = (dt > 20.f) ? dt : log1pf(expf(dt));
        sdt[p] = dtp;
        g_dA[row * HH + p] = expf(-expf(A_log[p]) * dtp);
    }
    const float* xrow = g_xconv + (size_t)row * DCONVCH;
    float s = 0.f;
    #pragma unroll
    for (int h = 0; h < HH; ++h) s += xrow[h * PP + p];
    g_xsh[(size_t)row * PP + p] = s * 0.125f;
    __syncthreads();
    const float Bn = xrow[DIN + p];                  // p == n here
    float* dst = g_bh + (size_t)row * (HH * GN_) + p;
    #pragma unroll
    for (int h = 0; h < HH; ++h)
        dst[h * GN_] = Bn * Bscale[h * GN_ + p] * sdt[h];
}

// ---------------- 5) selective scan: cp.async multistage pipeline ----------------
// Slot layout per timestep (168 floats): [0:16) bh (=B*bscale*dt), [16:32) C,
// [32:160) xsh, [160] dA, [161:168) pad.
#define SLOTF 168

__global__ void __launch_bounds__(128, 1)
scan_kernel() {
    __shared__ __align__(16) float ring[DST][SS][SLOTF];

    const int part = blockIdx.x, h = blockIdx.y, b = blockIdx.z;
    const int tid = threadIdx.x;                 // = p
    const int n0 = part * NPN;
    const int lane16 = tid & 15;
    const int tgrp = tid >> 4;                   // timestep-in-superstep this thread stages
    const size_t row0 = (size_t)b * LL;

    ull state[8];
    #pragma unroll
    for (int j = 0; j < 8; ++j) state[j] = 0ull;

    auto issue = [&](int s) {
        if (s < NSUP) {
            const size_t row = row0 + (size_t)s * SS + tgrp;
            float* dstT = &ring[s & (DST - 1)][tgrp][0];
            const float* bhrow   = g_bh + (row * HH + h) * GN_ + n0;
            const float* convrow = g_xconv + row * DCONVCH;
            const float* xshrow  = g_xsh + row * PP;
            #pragma unroll
            for (int c = lane16; c < 40; c += 16) {
                const float* src;
                float* dst;
                if (c < 4)      { src = bhrow + c * 4;                           dst = dstT + c * 4; }
                else if (c < 8) { src = convrow + DIN + GN_ + n0 + (c - 4) * 4;  dst = dstT + 16 + (c - 4) * 4; }
                else            { src = xshrow + (c - 8) * 4;                    dst = dstT + 32 + (c - 8) * 4; }
                cp_async16(smem_u32(dst), src);
            }
            if (lane16 == 8) cp_async4(smem_u32(dstT + 160), g_dA + row * HH + h);
        }
        CP_COMMIT();
    };

    #pragma unroll
    for (int s = 0; s < DST - 1; ++s) issue(s);

    float* yp = g_ypart + ((size_t)part * ROWS + row0) * DIN + (size_t)h * PP + tid;

    for (int s = 0; s < NSUP; ++s) {
        cp_wait<DST - 2>();        // stage s landed
        __syncthreads();           // visible to all warps; slot (s-1)%DST free for refill

        const float* slotp = &ring[s & (DST - 1)][0][0];
        #pragma unroll
        for (int i = 0; i < SS; ++i) {
            const float* s4 = slotp + i * SLOTF;
            const ull* s8 = (const ull*)s4;       // [0:8)=bh pairs, [8:16)=C pairs
            const float x = s4[32 + tid];
            const float dAv = s4[160];
            const ull dAp = f32x2_pack(dAv, dAv);
            const ull cfp = f32x2_pack(x, x);
            ull accA = 0ull, accB = 0ull;
            #pragma unroll
            for (int j = 0; j < 8; ++j) {
                state[j] = f32x2_fma(dAp, state[j], f32x2_mul(cfp, s8[j]));
                if (j & 1) accB = f32x2_fma(s8[8 + j], state[j], accB);
                else       accA = f32x2_fma(s8[8 + j], state[j], accA);
            }
            float2 a = f32x2_unpack(accA);
            float2 c = f32x2_unpack(accB);
            yp[(size_t)(s * SS + i) * DIN] = (a.x + a.y) + (c.x + c.y);
        }

        issue(s + DST - 1);        // refill slot (s-1)%DST
    }
}

// ---------------- 6) combine partials + D*x + gate + RMSNorm -> split bf16 ----------------
__global__ void combine_kernel(const float* __restrict__ D_param,
                               const float* __restrict__ rms_w) {
    const int row = blockIdx.x, tid = threadIdx.x;
    __shared__ float red[256];
    float yv[4];
    float sq = 0.f;
    #pragma unroll
    for (int q = 0; q < 4; ++q) {
        const int c = q * 256 + tid;
        float s = 0.f;
        #pragma unroll
        for (int part = 0; part < NPART; ++part)
            s += g_ypart[((size_t)part * ROWS + row) * DIN + c];
        s = fmaf(D_param[c >> 7], g_xsh[(size_t)row * PP + (c & 127)], s);
        const float z = g_zx[(size_t)row * DPROJP + c];
        const float yg = s * siluf(z);
        yv[q] = yg;
        sq += yg * yg;
    }
    red[tid] = sq; __syncthreads();
    #pragma unroll
    for (int s2 = 128; s2 > 0; s2 >>= 1) { if (tid < s2) red[tid] += red[tid + s2]; __syncthreads(); }
    const float rstd = rsqrtf(red[0] * (1.f / (float)DIN) + EPS_);
    #pragma unroll
    for (int q = 0; q < 4; ++q) {
        const int c = q * 256 + tid;
        float v = yv[q] * rstd * rms_w[c];
        __nv_bfloat16 h, l;
        split_bf16(v, h, l);
        g_yh[(size_t)row * DIN + c] = h;
        g_yl[(size_t)row * DIN + c] = l;
    }
}

// ---------------- launch ----------------
extern "C" void kernel_launch(void* const* d_in, const int* in_sizes, int n_in,
                              void* d_out, int out_size) {
    const float* u        = (const float*)d_in[0];
    const float* ln_gamma = (const float*)d_in[1];
    const float* ln_beta  = (const float*)d_in[2];
    const float* W_in     = (const float*)d_in[3];
    const float* conv_w   = (const float*)d_in[4];
    const float* conv_b   = (const float*)d_in[5];
    const float* dt_bias  = (const float*)d_in[6];
    const float* A_log    = (const float*)d_in[7];
    const float* D_param  = (const float*)d_in[8];
    const float* B_scale  = (const float*)d_in[9];
    const float* rms_w    = (const float*)d_in[10];
    const float* W_out    = (const float*)d_in[11];
    float* out = (float*)d_out;

    cudaFuncSetAttribute(mma_gemm_kernel,
                         cudaFuncAttributeMaxDynamicSharedMemorySize, GEMM_SMEM);

    __nv_bfloat16 *p_xh, *p_xl, *p_winh, *p_winl, *p_wouth, *p_woutl, *p_yh, *p_yl;
    float* p_zx;
    cudaGetSymbolAddress((void**)&p_xh, g_xh);
    cudaGetSymbolAddress((void**)&p_xl, g_xl);
    cudaGetSymbolAddress((void**)&p_winh, g_WinT_h);
    cudaGetSymbolAddress((void**)&p_winl, g_WinT_l);
    cudaGetSymbolAddress((void**)&p_wouth, g_WoutT_h);
    cudaGetSymbolAddress((void**)&p_woutl, g_WoutT_l);
    cudaGetSymbolAddress((void**)&p_yh, g_yh);
    cudaGetSymbolAddress((void**)&p_yl, g_yl);
    cudaGetSymbolAddress((void**)&p_zx, g_zx);

    ln_kernel<<<ROWS, 256>>>(u, ln_gamma, ln_beta);
    transpose_win_kernel<<<dim3(DPROJP / 32, DM / 32), dim3(32, 8)>>>(W_in);
    transpose_wout_kernel<<<dim3(DM / 32, DIN / 32), dim3(32, 8)>>>(W_out);

    // GEMM1: zx[8192 x 2560(pad)] = xn @ W_in  (split-bf16 HMMA, 128x256 tile)
    mma_gemm_kernel<<<dim3(DPROJP / 256, ROWS / 128), 256, GEMM_SMEM>>>(
        p_xh, p_xl, p_winh, p_winl, DM, p_zx, DPROJP, nullptr);

    conv_kernel<<<dim3(DCONVCH / 256, LL / CLT, BB), 256>>>(conv_w, conv_b);
    prep_kernel<<<ROWS, 128>>>(B_scale, dt_bias, A_log);

    scan_kernel<<<dim3(NPART, HH, BB), 128>>>();

    combine_kernel<<<ROWS, 256>>>(D_param, rms_w);

    // GEMM2: out[8192 x 256] = yg @ W_out + u
    mma_gemm_kernel<<<dim3(DM / 256, ROWS / 128), 256, GEMM_SMEM>>>(
        p_yh, p_yl, p_wouth, p_woutl, DIN, out, DM, u);
}

// round 8
// speedup vs baseline: 1.2075x; 1.2075x over previous
#include <cuda_runtime.h>
#include <cuda_bf16.h>
#include <cuda_fp16.h>
#include <math.h>
#include <stdint.h>

// ---------------- problem constants ----------------
#define BB 2
#define LL 4096
#define DM 256
#define DIN 1024          // D_INNER
#define GN_ 128           // NGROUPS*D_STATE
#define HH 8              // NHEADS
#define PP 128            // HEADDIM
#define DPROJ 2312        // D_IN_PROJ (logical)
#define DPROJP 2432       // padded to 19*128
#define DCONVCH 1280      // D_INNER + 2*GN
#define ROWS (BB*LL)      // 8192
#define EPS_ 1e-5f

#define NPART 8
#define NPN 16            // n per partition
#define SS 8              // scan superstep (timesteps per pipeline stage)
#define DST 4             // pipeline depth (stages)
#define NSUP (LL / SS)    // 512

// ---------------- scratch (static device allocations) ----------------
__device__ __align__(16) __nv_bfloat16 g_xh[(size_t)ROWS * DM];
__device__ __align__(16) __nv_bfloat16 g_xl[(size_t)ROWS * DM];
__device__ __align__(16) __nv_bfloat16 g_WinT_h[(size_t)DPROJP * DM];
__device__ __align__(16) __nv_bfloat16 g_WinT_l[(size_t)DPROJP * DM];
__device__ __align__(16) __nv_bfloat16 g_WoutT_h[(size_t)DM * DIN];
__device__ __align__(16) __nv_bfloat16 g_WoutT_l[(size_t)DM * DIN];
__device__ __align__(16) __nv_bfloat16 g_yh[(size_t)ROWS * DIN];
__device__ __align__(16) __nv_bfloat16 g_yl[(size_t)ROWS * DIN];
__device__ float g_zx[(size_t)ROWS * DPROJP];
__device__ float g_xconv[(size_t)ROWS * DCONVCH];
__device__ float g_dA[(size_t)ROWS * HH];
__device__ float g_xsh[(size_t)ROWS * PP];
__device__ float g_bh[(size_t)ROWS * HH * GN_];    // B*bscale*dt (33.5 MB)
__device__ __half g_ypart[(size_t)NPART * ROWS * DIN];   // fp16 partials (128 MB)

// ---------------- small helpers ----------------
__device__ __forceinline__ float siluf(float x) { return x / (1.f + expf(-x)); }

__device__ __forceinline__ void split_bf16(float v, __nv_bfloat16& h, __nv_bfloat16& l) {
    h = __float2bfloat16(v);
    l = __float2bfloat16(v - __bfloat162float(h));
}

typedef unsigned long long ull;
__device__ __forceinline__ ull f32x2_fma(ull a, ull b, ull c) {
    ull d; asm("fma.rn.f32x2 %0, %1, %2, %3;" : "=l"(d) : "l"(a), "l"(b), "l"(c)); return d;
}
__device__ __forceinline__ ull f32x2_mul(ull a, ull b) {
    ull d; asm("mul.rn.f32x2 %0, %1, %2;" : "=l"(d) : "l"(a), "l"(b)); return d;
}
__device__ __forceinline__ ull f32x2_pack(float lo, float hi) {
    ull d; asm("mov.b64 %0, {%1, %2};" : "=l"(d) : "f"(lo), "f"(hi)); return d;
}
__device__ __forceinline__ float2 f32x2_unpack(ull v) {
    float2 r; asm("mov.b64 {%0, %1}, %2;" : "=f"(r.x), "=f"(r.y) : "l"(v)); return r;
}

__device__ __forceinline__ uint32_t smem_u32(const void* p) {
    uint32_t a;
    asm("{ .reg .u64 t; cvta.to.shared.u64 t, %1; cvt.u32.u64 %0, t; }" : "=r"(a) : "l"(p));
    return a;
}

// ---------------- async copy helpers ----------------
__device__ __forceinline__ void cp_async16(uint32_t saddr, const void* gptr) {
    asm volatile("cp.async.cg.shared.global [%0], [%1], 16;"
                 :: "r"(saddr), "l"(gptr) : "memory");
}
__device__ __forceinline__ void cp_async4(uint32_t saddr, const void* gptr) {
    asm volatile("cp.async.ca.shared.global [%0], [%1], 4;"
                 :: "r"(saddr), "l"(gptr) : "memory");
}
#define CP_COMMIT() asm volatile("cp.async.commit_group;" ::: "memory")
template <int N> __device__ __forceinline__ void cp_wait() {
    asm volatile("cp.async.wait_group %0;" :: "n"(N) : "memory");
}

__device__ __forceinline__ void ldmatrix_x4(uint32_t* r, uint32_t addr) {
    asm volatile("ldmatrix.sync.aligned.m8n8.x4.shared.b16 {%0,%1,%2,%3}, [%4];"
                 : "=r"(r[0]), "=r"(r[1]), "=r"(r[2]), "=r"(r[3]) : "r"(addr));
}

__device__ __forceinline__ void mma_bf16(float* c, const uint32_t* a, uint32_t b0, uint32_t b1) {
    asm volatile(
        "mma.sync.aligned.m16n8k16.row.col.f32.bf16.bf16.f32 "
        "{%0,%1,%2,%3}, {%4,%5,%6,%7}, {%8,%9}, {%0,%1,%2,%3};"
        : "+f"(c[0]), "+f"(c[1]), "+f"(c[2]), "+f"(c[3])
        : "r"(a[0]), "r"(a[1]), "r"(a[2]), "r"(a[3]), "r"(b0), "r"(b1));
}

// ---------------- 1) LayerNorm -> split bf16 (single-pass, shuffle) ----------------
__global__ void ln_kernel(const float* __restrict__ u,
                          const float* __restrict__ gamma,
                          const float* __restrict__ beta) {
    __shared__ float w1[8], w2[8], bc[2];
    const int row = blockIdx.x, tid = threadIdx.x;
    const int wid = tid >> 5, lane = tid & 31;
    float v = u[(size_t)row * DM + tid];
    float s1 = v, s2 = v * v;
    #pragma unroll
    for (int o = 16; o > 0; o >>= 1) {
        s1 += __shfl_xor_sync(0xffffffffu, s1, o);
        s2 += __shfl_xor_sync(0xffffffffu, s2, o);
    }
    if (lane == 0) { w1[wid] = s1; w2[wid] = s2; }
    __syncthreads();
    if (wid == 0) {
        float a = (lane < 8) ? w1[lane] : 0.f;
        float b = (lane < 8) ? w2[lane] : 0.f;
        #pragma unroll
        for (int o = 4; o > 0; o >>= 1) {
            a += __shfl_xor_sync(0xffffffffu, a, o);
            b += __shfl_xor_sync(0xffffffffu, b, o);
        }
        if (lane == 0) {
            float mu = a * (1.f / 256.f);
            float var = b * (1.f / 256.f) - mu * mu;
            bc[0] = mu;
            bc[1] = rsqrtf(var + EPS_);
        }
    }
    __syncthreads();
    float xn = (v - bc[0]) * bc[1] * gamma[tid] + beta[tid];
    __nv_bfloat16 h, l;
    split_bf16(xn, h, l);
    g_xh[(size_t)row * DM + tid] = h;
    g_xl[(size_t)row * DM + tid] = l;
}

// ---------------- transposes + split of weights (tiled, coalesced) ----------------
__global__ void transpose_win_kernel(const float* __restrict__ W_in) {
    __shared__ float tile[32][33];
    const int tx = threadIdx.x, ty = threadIdx.y;        // 32 x 8
    const int n0 = blockIdx.x * 32, k0 = blockIdx.y * 32;
    #pragma unroll
    for (int dy = 0; dy < 32; dy += 8) {
        const int n = n0 + tx, k = k0 + ty + dy;
        tile[ty + dy][tx] = (n < DPROJ) ? W_in[(size_t)k * DPROJ + n] : 0.f;
    }
    __syncthreads();
    #pragma unroll
    for (int dy = 0; dy < 32; dy += 8) {
        const int n = n0 + ty + dy, k = k0 + tx;
        float v = tile[tx][ty + dy];
        __nv_bfloat16 h, l;
        split_bf16(v, h, l);
        g_WinT_h[(size_t)n * DM + k] = h;
        g_WinT_l[(size_t)n * DM + k] = l;
    }
}

__global__ void transpose_wout_kernel(const float* __restrict__ W_out) {
    __shared__ float tile[32][33];
    const int tx = threadIdx.x, ty = threadIdx.y;        // 32 x 8
    const int n0 = blockIdx.x * 32, k0 = blockIdx.y * 32;
    #pragma unroll
    for (int dy = 0; dy < 32; dy += 8) {
        tile[ty + dy][tx] = W_out[(size_t)(k0 + ty + dy) * DM + n0 + tx];
    }
    __syncthreads();
    #pragma unroll
    for (int dy = 0; dy < 32; dy += 8) {
        const int n = n0 + ty + dy, k = k0 + tx;
        float v = tile[tx][ty + dy];
        __nv_bfloat16 h, l;
        split_bf16(v, h, l);
        g_WoutT_h[(size_t)n * DIN + k] = h;
        g_WoutT_l[(size_t)n * DIN + k] = l;
    }
}

// ---------------- 2) split-bf16 GEMM on mma.sync (HMMA), 128x128, 3-stage ----------------
#define STR 40   // smem row stride (bf16): conflict-free for ldmatrix
#define ABUF (128 * STR * 2)          // bytes per stage per operand (10240)
#define GEMM_SMEM (6 * ABUF)          // 61440

__global__ void __launch_bounds__(256)
mma_gemm_kernel(const __nv_bfloat16* __restrict__ Ah,
                const __nv_bfloat16* __restrict__ Al,
                const __nv_bfloat16* __restrict__ Bh,
                const __nv_bfloat16* __restrict__ Bl,
                int Kin,
                float* __restrict__ C, int ldc,
                const float* __restrict__ Cadd) {
    extern __shared__ char dsmem[];
    const uint32_t sbase = smem_u32(dsmem);

    const int tid = threadIdx.x;
    const int wid = tid >> 5, lid = tid & 31;
    const int wm = wid >> 2;           // 0..1
    const int wn = wid & 3;            // 0..3
    const int tileRow = blockIdx.y * 128;
    const int tileCol = blockIdx.x * 128;

    const int stRow = tid >> 1;
    const int stSeg = (tid & 1) * 16;
    const uint32_t stOffB = (uint32_t)(stRow * STR + stSeg) * 2;

    const int aRowOff = (lid & 7) + ((lid >> 3) & 1) * 8;
    const int aKOff   = (lid >> 4) * 8;
    const int bNOff   = (lid & 7) + ((lid >> 4) & 1) * 8;
    const int bKOff   = ((lid >> 3) & 1) * 8;

    float acc[4][4][4];
    #pragma unroll
    for (int i = 0; i < 4; ++i)
        #pragma unroll
        for (int j = 0; j < 4; ++j)
            #pragma unroll
            for (int q = 0; q < 4; ++q) acc[i][j][q] = 0.f;

    const int cps = Kin / 32;
    const int T = 3 * cps;

    auto issue = [&](int c) {
        if (c < T) {
            const int seg = c / cps;
            const int kc = c - seg * cps;
            const __nv_bfloat16* Ag = (seg == 1) ? Al : Ah;
            const __nv_bfloat16* Bg = (seg == 2) ? Bl : Bh;
            const __nv_bfloat16* ga = Ag + (size_t)(tileRow + stRow) * Kin + kc * 32 + stSeg;
            const __nv_bfloat16* gb = Bg + (size_t)(tileCol + stRow) * Kin + kc * 32 + stSeg;
            const int buf = c % 3;
            const uint32_t sa = sbase + (uint32_t)buf * ABUF + stOffB;
            const uint32_t sb = sbase + (uint32_t)(3 + buf) * ABUF + stOffB;
            cp_async16(sa, ga);
            cp_async16(sa + 16, ga + 8);
            cp_async16(sb, gb);
            cp_async16(sb + 16, gb + 8);
        }
        CP_COMMIT();
    };

    issue(0); issue(1);
    for (int c = 0; c < T; ++c) {
        cp_wait<1>();
        __syncthreads();

        const int buf = c % 3;
        const uint32_t aB = sbase + (uint32_t)buf * ABUF;
        const uint32_t bB = sbase + (uint32_t)(3 + buf) * ABUF;
        #pragma unroll
        for (int kk = 0; kk < 32; kk += 16) {
            uint32_t afr[4][4];
            #pragma unroll
            for (int mt = 0; mt < 4; ++mt) {
                uint32_t addr = aB + (uint32_t)((wm * 64 + mt * 16 + aRowOff) * STR + kk + aKOff) * 2;
                ldmatrix_x4(afr[mt], addr);
            }
            uint32_t bfr[2][4];
            #pragma unroll
            for (int pr = 0; pr < 2; ++pr) {
                uint32_t addr = bB + (uint32_t)((wn * 32 + pr * 16 + bNOff) * STR + kk + bKOff) * 2;
                ldmatrix_x4(bfr[pr], addr);
            }
            #pragma unroll
            for (int mt = 0; mt < 4; ++mt)
                #pragma unroll
                for (int nt = 0; nt < 4; ++nt) {
                    const uint32_t* bp = bfr[nt >> 1];
                    const int hi = (nt & 1) * 2;
                    mma_bf16(acc[mt][nt], afr[mt], bp[hi], bp[hi + 1]);
                }
        }
        issue(c + 2);
    }

    const int gID = lid >> 2, qid = lid & 3;
    #pragma unroll
    for (int mt = 0; mt < 4; ++mt) {
        const int r0 = tileRow + wm * 64 + mt * 16 + gID;
        #pragma unroll
        for (int nt = 0; nt < 4; ++nt) {
            const int col = tileCol + wn * 32 + nt * 8 + qid * 2;
            float2 v0 = make_float2(acc[mt][nt][0], acc[mt][nt][1]);
            float2 v1 = make_float2(acc[mt][nt][2], acc[mt][nt][3]);
            if (Cadd) {
                const float2 a0 = *(const float2*)(Cadd + (size_t)r0 * ldc + col);
                const float2 a1 = *(const float2*)(Cadd + (size_t)(r0 + 8) * ldc + col);
                v0.x += a0.x; v0.y += a0.y;
                v1.x += a1.x; v1.y += a1.y;
            }
            *(float2*)(C + (size_t)r0 * ldc + col) = v0;
            *(float2*)(C + (size_t)(r0 + 8) * ldc + col) = v1;
        }
    }
}

// ---------------- 3) causal depthwise conv (K=4) + SiLU, register ring over l ----------------
#define CLT 16
__global__ void conv_kernel(const float* __restrict__ conv_w,
                            const float* __restrict__ conv_b) {
    const int c = blockIdx.x * 256 + threadIdx.x;   // 0..1279 (grid.x = 5)
    const int l0 = blockIdx.y * CLT;
    const int b = blockIdx.z;
    const size_t base = ((size_t)b * LL) * DPROJP + DIN + c;
    const float w0 = conv_w[c * 4 + 0], w1 = conv_w[c * 4 + 1];
    const float w2 = conv_w[c * 4 + 2], w3 = conv_w[c * 4 + 3];
    const float bias = conv_b[c];

    float x0 = 0.f, x1 = 0.f, x2 = 0.f;
    if (l0 > 0) {
        x0 = g_zx[base + (size_t)(l0 - 3) * DPROJP];
        x1 = g_zx[base + (size_t)(l0 - 2) * DPROJP];
        x2 = g_zx[base + (size_t)(l0 - 1) * DPROJP];
    }
    #pragma unroll
    for (int i = 0; i < CLT; ++i) {
        const float x3 = g_zx[base + (size_t)(l0 + i) * DPROJP];
        float acc = fmaf(x0, w0, bias);
        acc = fmaf(x1, w1, acc);
        acc = fmaf(x2, w2, acc);
        acc = fmaf(x3, w3, acc);
        g_xconv[((size_t)b * LL + l0 + i) * DCONVCH + c] = siluf(acc);
        x0 = x1; x1 = x2; x2 = x3;
    }
}

// ---------------- 4) prep: dt/dA + x_shared mean + prescaled B (fused) ----------------
__global__ void prep_kernel(const float* __restrict__ Bscale,
                            const float* __restrict__ dt_bias,
                            const float* __restrict__ A_log) {
    __shared__ float sdt[HH];
    const int row = blockIdx.x, p = threadIdx.x;    // 128 threads
    if (p < HH) {
        float dt = g_zx[(size_t)row * DPROJP + 2304 + p] + dt_bias[p];
        float dtp = (dt > 20.f) ? dt : log1pf(expf(dt));
        sdt[p] = dtp;
        g_dA[row * HH + p] = expf(-expf(A_log[p]) * dtp);
    }
    const float* xrow = g_xconv + (size_t)row * DCONVCH;
    float s = 0.f;
    #pragma unroll
    for (int h = 0; h < HH; ++h) s += xrow[h * PP + p];
    g_xsh[(size_t)row * PP + p] = s * 0.125f;
    __syncthreads();
    const float Bn = xrow[DIN + p];                  // p == n here
    float* dst = g_bh + (size_t)row * (HH * GN_) + p;
    #pragma unroll
    for (int h = 0; h < HH; ++h)
        dst[h * GN_] = Bn * Bscale[h * GN_ + p] * sdt[h];
}

// ---------------- 5) selective scan: cp.async multistage pipeline ----------------
// Slot layout per timestep (168 floats): [0:16) bh (=B*bscale*dt), [16:32) C,
// [32:160) xsh, [160] dA, [161:168) pad.
#define SLOTF 168

__global__ void __launch_bounds__(128, 1)
scan_kernel() {
    __shared__ __align__(16) float ring[DST][SS][SLOTF];

    const int part = blockIdx.x, h = blockIdx.y, b = blockIdx.z;
    const int tid = threadIdx.x;                 // = p
    const int n0 = part * NPN;
    const int lane16 = tid & 15;
    const int tgrp = tid >> 4;                   // timestep-in-superstep this thread stages
    const size_t row0 = (size_t)b * LL;

    ull state[8];
    #pragma unroll
    for (int j = 0; j < 8; ++j) state[j] = 0ull;

    auto issue = [&](int s) {
        if (s < NSUP) {
            const size_t row = row0 + (size_t)s * SS + tgrp;
            float* dstT = &ring[s & (DST - 1)][tgrp][0];
            const float* bhrow   = g_bh + (row * HH + h) * GN_ + n0;
            const float* convrow = g_xconv + row * DCONVCH;
            const float* xshrow  = g_xsh + row * PP;
            #pragma unroll
            for (int c = lane16; c < 40; c += 16) {
                const float* src;
                float* dst;
                if (c < 4)      { src = bhrow + c * 4;                           dst = dstT + c * 4; }
                else if (c < 8) { src = convrow + DIN + GN_ + n0 + (c - 4) * 4;  dst = dstT + 16 + (c - 4) * 4; }
                else            { src = xshrow + (c - 8) * 4;                    dst = dstT + 32 + (c - 8) * 4; }
                cp_async16(smem_u32(dst), src);
            }
            if (lane16 == 8) cp_async4(smem_u32(dstT + 160), g_dA + row * HH + h);
        }
        CP_COMMIT();
    };

    #pragma unroll
    for (int s = 0; s < DST - 1; ++s) issue(s);

    __half* yp = g_ypart + ((size_t)part * ROWS + row0) * DIN + (size_t)h * PP + tid;

    for (int s = 0; s < NSUP; ++s) {
        cp_wait<DST - 2>();        // stage s landed
        __syncthreads();           // visible to all warps; slot (s-1)%DST free for refill

        const float* slotp = &ring[s & (DST - 1)][0][0];
        #pragma unroll
        for (int i = 0; i < SS; ++i) {
            const float* s4 = slotp + i * SLOTF;
            const ull* s8 = (const ull*)s4;       // [0:8)=bh pairs, [8:16)=C pairs
            const float x = s4[32 + tid];
            const float dAv = s4[160];
            const ull dAp = f32x2_pack(dAv, dAv);
            const ull cfp = f32x2_pack(x, x);
            ull accA = 0ull, accB = 0ull;
            #pragma unroll
            for (int j = 0; j < 8; ++j) {
                state[j] = f32x2_fma(dAp, state[j], f32x2_mul(cfp, s8[j]));
                if (j & 1) accB = f32x2_fma(s8[8 + j], state[j], accB);
                else       accA = f32x2_fma(s8[8 + j], state[j], accA);
            }
            float2 a = f32x2_unpack(accA);
            float2 c = f32x2_unpack(accB);
            yp[(size_t)(s * SS + i) * DIN] = __float2half((a.x + a.y) + (c.x + c.y));
        }

        issue(s + DST - 1);        // refill slot (s-1)%DST
    }
}

// ---------------- 6) combine partials + D*x + gate + RMSNorm -> split bf16 ----------------
__global__ void combine_kernel(const float* __restrict__ D_param,
                               const float* __restrict__ rms_w) {
    const int row = blockIdx.x, tid = threadIdx.x;
    __shared__ float red[256];
    float yv[4];
    float sq = 0.f;
    #pragma unroll
    for (int q = 0; q < 4; ++q) {
        const int c = q * 256 + tid;
        float s = 0.f;
        #pragma unroll
        for (int part = 0; part < NPART; ++part)
            s += __half2float(g_ypart[((size_t)part * ROWS + row) * DIN + c]);
        s = fmaf(D_param[c >> 7], g_xsh[(size_t)row * PP + (c & 127)], s);
        const float z = g_zx[(size_t)row * DPROJP + c];
        const float yg = s * siluf(z);
        yv[q] = yg;
        sq += yg * yg;
    }
    red[tid] = sq; __syncthreads();
    #pragma unroll
    for (int s2 = 128; s2 > 0; s2 >>= 1) { if (tid < s2) red[tid] += red[tid + s2]; __syncthreads(); }
    const float rstd = rsqrtf(red[0] * (1.f / (float)DIN) + EPS_);
    #pragma unroll
    for (int q = 0; q < 4; ++q) {
        const int c = q * 256 + tid;
        float v = yv[q] * rstd * rms_w[c];
        __nv_bfloat16 h, l;
        split_bf16(v, h, l);
        g_yh[(size_t)row * DIN + c] = h;
        g_yl[(size_t)row * DIN + c] = l;
    }
}

// ---------------- launch ----------------
extern "C" void kernel_launch(void* const* d_in, const int* in_sizes, int n_in,
                              void* d_out, int out_size) {
    const float* u        = (const float*)d_in[0];
    const float* ln_gamma = (const float*)d_in[1];
    const float* ln_beta  = (const float*)d_in[2];
    const float* W_in     = (const float*)d_in[3];
    const float* conv_w   = (const float*)d_in[4];
    const float* conv_b   = (const float*)d_in[5];
    const float* dt_bias  = (const float*)d_in[6];
    const float* A_log    = (const float*)d_in[7];
    const float* D_param  = (const float*)d_in[8];
    const float* B_scale  = (const float*)d_in[9];
    const float* rms_w    = (const float*)d_in[10];
    const float* W_out    = (const float*)d_in[11];
    float* out = (float*)d_out;

    cudaFuncSetAttribute(mma_gemm_kernel,
                         cudaFuncAttributeMaxDynamicSharedMemorySize, GEMM_SMEM);

    __nv_bfloat16 *p_xh, *p_xl, *p_winh, *p_winl, *p_wouth, *p_woutl, *p_yh, *p_yl;
    float* p_zx;
    cudaGetSymbolAddress((void**)&p_xh, g_xh);
    cudaGetSymbolAddress((void**)&p_xl, g_xl);
    cudaGetSymbolAddress((void**)&p_winh, g_WinT_h);
    cudaGetSymbolAddress((void**)&p_winl, g_WinT_l);
    cudaGetSymbolAddress((void**)&p_wouth, g_WoutT_h);
    cudaGetSymbolAddress((void**)&p_woutl, g_WoutT_l);
    cudaGetSymbolAddress((void**)&p_yh, g_yh);
    cudaGetSymbolAddress((void**)&p_yl, g_yl);
    cudaGetSymbolAddress((void**)&p_zx, g_zx);

    ln_kernel<<<ROWS, 256>>>(u, ln_gamma, ln_beta);
    transpose_win_kernel<<<dim3(DPROJP / 32, DM / 32), dim3(32, 8)>>>(W_in);
    transpose_wout_kernel<<<dim3(DM / 32, DIN / 32), dim3(32, 8)>>>(W_out);

    // GEMM1: zx[8192 x 2432(pad)] = xn @ W_in  (split-bf16 HMMA, 128x128 tile)
    mma_gemm_kernel<<<dim3(DPROJP / 128, ROWS / 128), 256, GEMM_SMEM>>>(
        p_xh, p_xl, p_winh, p_winl, DM, p_zx, DPROJP, nullptr);

    conv_kernel<<<dim3(DCONVCH / 256, LL / CLT, BB), 256>>>(conv_w, conv_b);
    prep_kernel<<<ROWS, 128>>>(B_scale, dt_bias, A_log);

    scan_kernel<<<dim3(NPART, HH, BB), 128>>>();

    combine_kernel<<<ROWS, 256>>>(D_param, rms_w);

    // GEMM2: out[8192 x 256] = yg @ W_out + u
    mma_gemm_kernel<<<dim3(DM / 128, ROWS / 128), 256, GEMM_SMEM>>>(
        p_yh, p_yl, p_wouth, p_woutl, DIN, out, DM, u);
}

// round 9
// speedup vs baseline: 1.2729x; 1.0542x over previous
#include <cuda_runtime.h>
#include <cuda_bf16.h>
#include <cuda_fp16.h>
#include <math.h>
#include <stdint.h>

// ---------------- problem constants ----------------
#define BB 2
#define LL 4096
#define DM 256
#define DIN 1024          // D_INNER
#define GN_ 128           // NGROUPS*D_STATE
#define HH 8              // NHEADS
#define PP 128            // HEADDIM
#define DPROJ 2312        // D_IN_PROJ (logical)
#define DPROJP 2432       // padded to 19*128
#define DCONVCH 1280      // D_INNER + 2*GN
#define ROWS (BB*LL)      // 8192
#define EPS_ 1e-5f

#define NPART 8
#define NPN 16            // n per partition
#define SS 8              // scan superstep (timesteps per pipeline stage)
#define DST 4             // pipeline depth (stages)
#define NSUP (LL / SS)    // 512

// ---------------- scratch (static device allocations) ----------------
__device__ __align__(16) __nv_bfloat16 g_xh[(size_t)ROWS * DM];
__device__ __align__(16) __nv_bfloat16 g_xl[(size_t)ROWS * DM];
__device__ __align__(16) __nv_bfloat16 g_WinT_h[(size_t)DPROJP * DM];
__device__ __align__(16) __nv_bfloat16 g_WinT_l[(size_t)DPROJP * DM];
__device__ __align__(16) __nv_bfloat16 g_WoutT_h[(size_t)DM * DIN];
__device__ __align__(16) __nv_bfloat16 g_WoutT_l[(size_t)DM * DIN];
__device__ __align__(16) __nv_bfloat16 g_yh[(size_t)ROWS * DIN];
__device__ __align__(16) __nv_bfloat16 g_yl[(size_t)ROWS * DIN];
__device__ float g_zx[(size_t)ROWS * DPROJP];
__device__ float g_xconv[(size_t)ROWS * DCONVCH];
__device__ float g_dA[(size_t)ROWS * HH];
__device__ float g_xsh[(size_t)ROWS * PP];
__device__ float g_bh[(size_t)ROWS * HH * GN_];    // B*bscale*dt (33.5 MB)
__device__ __align__(16) __half g_ypart[(size_t)NPART * ROWS * DIN];   // fp16 partials (128 MB)

// ---------------- small helpers ----------------
__device__ __forceinline__ float siluf(float x) { return x / (1.f + expf(-x)); }

__device__ __forceinline__ void split_bf16(float v, __nv_bfloat16& h, __nv_bfloat16& l) {
    h = __float2bfloat16(v);
    l = __float2bfloat16(v - __bfloat162float(h));
}

typedef unsigned long long ull;
__device__ __forceinline__ ull f32x2_fma(ull a, ull b, ull c) {
    ull d; asm("fma.rn.f32x2 %0, %1, %2, %3;" : "=l"(d) : "l"(a), "l"(b), "l"(c)); return d;
}
__device__ __forceinline__ ull f32x2_mul(ull a, ull b) {
    ull d; asm("mul.rn.f32x2 %0, %1, %2;" : "=l"(d) : "l"(a), "l"(b)); return d;
}
__device__ __forceinline__ ull f32x2_pack(float lo, float hi) {
    ull d; asm("mov.b64 %0, {%1, %2};" : "=l"(d) : "f"(lo), "f"(hi)); return d;
}
__device__ __forceinline__ float2 f32x2_unpack(ull v) {
    float2 r; asm("mov.b64 {%0, %1}, %2;" : "=f"(r.x), "=f"(r.y) : "l"(v)); return r;
}

__device__ __forceinline__ uint32_t smem_u32(const void* p) {
    uint32_t a;
    asm("{ .reg .u64 t; cvta.to.shared.u64 t, %1; cvt.u32.u64 %0, t; }" : "=r"(a) : "l"(p));
    return a;
}

// ---------------- async copy helpers ----------------
__device__ __forceinline__ void cp_async16(uint32_t saddr, const void* gptr) {
    asm volatile("cp.async.cg.shared.global [%0], [%1], 16;"
                 :: "r"(saddr), "l"(gptr) : "memory");
}
__device__ __forceinline__ void cp_async4(uint32_t saddr, const void* gptr) {
    asm volatile("cp.async.ca.shared.global [%0], [%1], 4;"
                 :: "r"(saddr), "l"(gptr) : "memory");
}
#define CP_COMMIT() asm volatile("cp.async.commit_group;" ::: "memory")
template <int N> __device__ __forceinline__ void cp_wait() {
    asm volatile("cp.async.wait_group %0;" :: "n"(N) : "memory");
}

__device__ __forceinline__ void ldmatrix_x4(uint32_t* r, uint32_t addr) {
    asm volatile("ldmatrix.sync.aligned.m8n8.x4.shared.b16 {%0,%1,%2,%3}, [%4];"
                 : "=r"(r[0]), "=r"(r[1]), "=r"(r[2]), "=r"(r[3]) : "r"(addr));
}

__device__ __forceinline__ void mma_bf16(float* c, const uint32_t* a, uint32_t b0, uint32_t b1) {
    asm volatile(
        "mma.sync.aligned.m16n8k16.row.col.f32.bf16.bf16.f32 "
        "{%0,%1,%2,%3}, {%4,%5,%6,%7}, {%8,%9}, {%0,%1,%2,%3};"
        : "+f"(c[0]), "+f"(c[1]), "+f"(c[2]), "+f"(c[3])
        : "r"(a[0]), "r"(a[1]), "r"(a[2]), "r"(a[3]), "r"(b0), "r"(b1));
}

// ---------------- 1) LayerNorm -> split bf16 (single-pass, shuffle) ----------------
__global__ void ln_kernel(const float* __restrict__ u,
                          const float* __restrict__ gamma,
                          const float* __restrict__ beta) {
    __shared__ float w1[8], w2[8], bc[2];
    const int row = blockIdx.x, tid = threadIdx.x;
    const int wid = tid >> 5, lane = tid & 31;
    float v = u[(size_t)row * DM + tid];
    float s1 = v, s2 = v * v;
    #pragma unroll
    for (int o = 16; o > 0; o >>= 1) {
        s1 += __shfl_xor_sync(0xffffffffu, s1, o);
        s2 += __shfl_xor_sync(0xffffffffu, s2, o);
    }
    if (lane == 0) { w1[wid] = s1; w2[wid] = s2; }
    __syncthreads();
    if (wid == 0) {
        float a = (lane < 8) ? w1[lane] : 0.f;
        float b = (lane < 8) ? w2[lane] : 0.f;
        #pragma unroll
        for (int o = 4; o > 0; o >>= 1) {
            a += __shfl_xor_sync(0xffffffffu, a, o);
            b += __shfl_xor_sync(0xffffffffu, b, o);
        }
        if (lane == 0) {
            float mu = a * (1.f / 256.f);
            float var = b * (1.f / 256.f) - mu * mu;
            bc[0] = mu;
            bc[1] = rsqrtf(var + EPS_);
        }
    }
    __syncthreads();
    float xn = (v - bc[0]) * bc[1] * gamma[tid] + beta[tid];
    __nv_bfloat16 h, l;
    split_bf16(xn, h, l);
    g_xh[(size_t)row * DM + tid] = h;
    g_xl[(size_t)row * DM + tid] = l;
}

// ---------------- transposes + split of weights (tiled, coalesced) ----------------
__global__ void transpose_win_kernel(const float* __restrict__ W_in) {
    __shared__ float tile[32][33];
    const int tx = threadIdx.x, ty = threadIdx.y;        // 32 x 8
    const int n0 = blockIdx.x * 32, k0 = blockIdx.y * 32;
    #pragma unroll
    for (int dy = 0; dy < 32; dy += 8) {
        const int n = n0 + tx, k = k0 + ty + dy;
        tile[ty + dy][tx] = (n < DPROJ) ? W_in[(size_t)k * DPROJ + n] : 0.f;
    }
    __syncthreads();
    #pragma unroll
    for (int dy = 0; dy < 32; dy += 8) {
        const int n = n0 + ty + dy, k = k0 + tx;
        float v = tile[tx][ty + dy];
        __nv_bfloat16 h, l;
        split_bf16(v, h, l);
        g_WinT_h[(size_t)n * DM + k] = h;
        g_WinT_l[(size_t)n * DM + k] = l;
    }
}

__global__ void transpose_wout_kernel(const float* __restrict__ W_out) {
    __shared__ float tile[32][33];
    const int tx = threadIdx.x, ty = threadIdx.y;        // 32 x 8
    const int n0 = blockIdx.x * 32, k0 = blockIdx.y * 32;
    #pragma unroll
    for (int dy = 0; dy < 32; dy += 8) {
        tile[ty + dy][tx] = W_out[(size_t)(k0 + ty + dy) * DM + n0 + tx];
    }
    __syncthreads();
    #pragma unroll
    for (int dy = 0; dy < 32; dy += 8) {
        const int n = n0 + ty + dy, k = k0 + tx;
        float v = tile[tx][ty + dy];
        __nv_bfloat16 h, l;
        split_bf16(v, h, l);
        g_WoutT_h[(size_t)n * DIN + k] = h;
        g_WoutT_l[(size_t)n * DIN + k] = l;
    }
}

// ---------------- 2) split-bf16 GEMM on mma.sync (HMMA), 128x128, 3-stage ----------------
#define STR 40   // smem row stride (bf16): conflict-free for ldmatrix
#define ABUF (128 * STR * 2)          // bytes per stage per operand (10240)
#define GEMM_SMEM (6 * ABUF)          // 61440

template <int CPS>
__global__ void __launch_bounds__(256)
mma_gemm_kernel(const __nv_bfloat16* __restrict__ Ah,
                const __nv_bfloat16* __restrict__ Al,
                const __nv_bfloat16* __restrict__ Bh,
                const __nv_bfloat16* __restrict__ Bl,
                float* __restrict__ C, int ldc,
                const float* __restrict__ Cadd) {
    constexpr int Kin = CPS * 32;
    constexpr int T = 3 * CPS;
    extern __shared__ char dsmem[];
    const uint32_t sbase = smem_u32(dsmem);

    const int tid = threadIdx.x;
    const int wid = tid >> 5, lid = tid & 31;
    const int wm = wid >> 2;           // 0..1
    const int wn = wid & 3;            // 0..3
    const int tileRow = blockIdx.y * 128;
    const int tileCol = blockIdx.x * 128;

    const int stRow = tid >> 1;
    const int stSeg = (tid & 1) * 16;
    const uint32_t stOffB = (uint32_t)(stRow * STR + stSeg) * 2;

    const int aRowOff = (lid & 7) + ((lid >> 3) & 1) * 8;
    const int aKOff   = (lid >> 4) * 8;
    const int bNOff   = (lid & 7) + ((lid >> 4) & 1) * 8;
    const int bKOff   = ((lid >> 3) & 1) * 8;

    float acc[4][4][4];
    #pragma unroll
    for (int i = 0; i < 4; ++i)
        #pragma unroll
        for (int j = 0; j < 4; ++j)
            #pragma unroll
            for (int q = 0; q < 4; ++q) acc[i][j][q] = 0.f;

    auto issue = [&](int c) {
        if (c < T) {
            const int seg = c / CPS;
            const int kc = c - seg * CPS;
            const __nv_bfloat16* Ag = (seg == 1) ? Al : Ah;
            const __nv_bfloat16* Bg = (seg == 2) ? Bl : Bh;
            const __nv_bfloat16* ga = Ag + (size_t)(tileRow + stRow) * Kin + kc * 32 + stSeg;
            const __nv_bfloat16* gb = Bg + (size_t)(tileCol + stRow) * Kin + kc * 32 + stSeg;
            const int buf = c % 3;
            const uint32_t sa = sbase + (uint32_t)buf * ABUF + stOffB;
            const uint32_t sb = sbase + (uint32_t)(3 + buf) * ABUF + stOffB;
            cp_async16(sa, ga);
            cp_async16(sa + 16, ga + 8);
            cp_async16(sb, gb);
            cp_async16(sb + 16, gb + 8);
        }
        CP_COMMIT();
    };

    issue(0); issue(1);
    for (int c = 0; c < T; ++c) {
        cp_wait<1>();
        __syncthreads();

        const int buf = c % 3;
        const uint32_t aB = sbase + (uint32_t)buf * ABUF;
        const uint32_t bB = sbase + (uint32_t)(3 + buf) * ABUF;

        // load all fragments for this chunk first
        uint32_t afr[2][4][4];
        uint32_t bfr[2][2][4];
        #pragma unroll
        for (int kk2 = 0; kk2 < 2; ++kk2) {
            const int kk = kk2 * 16;
            #pragma unroll
            for (int mt = 0; mt < 4; ++mt) {
                uint32_t addr = aB + (uint32_t)((wm * 64 + mt * 16 + aRowOff) * STR + kk + aKOff) * 2;
                ldmatrix_x4(afr[kk2][mt], addr);
            }
            #pragma unroll
            for (int pr = 0; pr < 2; ++pr) {
                uint32_t addr = bB + (uint32_t)((wn * 32 + pr * 16 + bNOff) * STR + kk + bKOff) * 2;
                ldmatrix_x4(bfr[kk2][pr], addr);
            }
        }

        // refill next-next stage while MMAs run (buffer (c+2)%3 consumed at c-1, safe)
        issue(c + 2);

        #pragma unroll
        for (int kk2 = 0; kk2 < 2; ++kk2)
            #pragma unroll
            for (int mt = 0; mt < 4; ++mt)
                #pragma unroll
                for (int nt = 0; nt < 4; ++nt) {
                    const uint32_t* bp = bfr[kk2][nt >> 1];
                    const int hi = (nt & 1) * 2;
                    mma_bf16(acc[mt][nt], afr[kk2][mt], bp[hi], bp[hi + 1]);
                }
    }

    const int gID = lid >> 2, qid = lid & 3;
    #pragma unroll
    for (int mt = 0; mt < 4; ++mt) {
        const int r0 = tileRow + wm * 64 + mt * 16 + gID;
        #pragma unroll
        for (int nt = 0; nt < 4; ++nt) {
            const int col = tileCol + wn * 32 + nt * 8 + qid * 2;
            float2 v0 = make_float2(acc[mt][nt][0], acc[mt][nt][1]);
            float2 v1 = make_float2(acc[mt][nt][2], acc[mt][nt][3]);
            if (Cadd) {
                const float2 a0 = *(const float2*)(Cadd + (size_t)r0 * ldc + col);
                const float2 a1 = *(const float2*)(Cadd + (size_t)(r0 + 8) * ldc + col);
                v0.x += a0.x; v0.y += a0.y;
                v1.x += a1.x; v1.y += a1.y;
            }
            *(float2*)(C + (size_t)r0 * ldc + col) = v0;
            *(float2*)(C + (size_t)(r0 + 8) * ldc + col) = v1;
        }
    }
}

// ---------------- 3) causal depthwise conv (K=4) + SiLU, register ring over l ----------------
#define CLT 16
__global__ void conv_kernel(const float* __restrict__ conv_w,
                            const float* __restrict__ conv_b) {
    const int c = blockIdx.x * 256 + threadIdx.x;   // 0..1279 (grid.x = 5)
    const int l0 = blockIdx.y * CLT;
    const int b = blockIdx.z;
    const size_t base = ((size_t)b * LL) * DPROJP + DIN + c;
    const float w0 = conv_w[c * 4 + 0], w1 = conv_w[c * 4 + 1];
    const float w2 = conv_w[c * 4 + 2], w3 = conv_w[c * 4 + 3];
    const float bias = conv_b[c];

    float x0 = 0.f, x1 = 0.f, x2 = 0.f;
    if (l0 > 0) {
        x0 = g_zx[base + (size_t)(l0 - 3) * DPROJP];
        x1 = g_zx[base + (size_t)(l0 - 2) * DPROJP];
        x2 = g_zx[base + (size_t)(l0 - 1) * DPROJP];
    }
    #pragma unroll
    for (int i = 0; i < CLT; ++i) {
        const float x3 = g_zx[base + (size_t)(l0 + i) * DPROJP];
        float acc = fmaf(x0, w0, bias);
        acc = fmaf(x1, w1, acc);
        acc = fmaf(x2, w2, acc);
        acc = fmaf(x3, w3, acc);
        g_xconv[((size_t)b * LL + l0 + i) * DCONVCH + c] = siluf(acc);
        x0 = x1; x1 = x2; x2 = x3;
    }
}

// ---------------- 4) prep: dt/dA + x_shared mean + prescaled B (fused) ----------------
__global__ void prep_kernel(const float* __restrict__ Bscale,
                            const float* __restrict__ dt_bias,
                            const float* __restrict__ A_log) {
    __shared__ float sdt[HH];
    const int row = blockIdx.x, p = threadIdx.x;    // 128 threads
    if (p < HH) {
        float dt = g_zx[(size_t)row * DPROJP + 2304 + p] + dt_bias[p];
        float dtp = (dt > 20.f) ? dt : log1pf(expf(dt));
        sdt[p] = dtp;
        g_dA[row * HH + p] = expf(-expf(A_log[p]) * dtp);
    }
    const float* xrow = g_xconv + (size_t)row * DCONVCH;
    float s = 0.f;
    #pragma unroll
    for (int h = 0; h < HH; ++h) s += xrow[h * PP + p];
    g_xsh[(size_t)row * PP + p] = s * 0.125f;
    __syncthreads();
    const float Bn = xrow[DIN + p];                  // p == n here
    float* dst = g_bh + (size_t)row * (HH * GN_) + p;
    #pragma unroll
    for (int h = 0; h < HH; ++h)
        dst[h * GN_] = Bn * Bscale[h * GN_ + p] * sdt[h];
}

// ---------------- 5) selective scan: cp.async multistage pipeline ----------------
// Slot layout per timestep (168 floats): [0:16) bh (=B*bscale*dt), [16:32) C,
// [32:160) xsh, [160] dA, [161:168) pad.
#define SLOTF 168

__global__ void __launch_bounds__(128, 1)
scan_kernel() {
    __shared__ __align__(16) float ring[DST][SS][SLOTF];

    const int part = blockIdx.x, h = blockIdx.y, b = blockIdx.z;
    const int tid = threadIdx.x;                 // = p
    const int n0 = part * NPN;
    const int lane16 = tid & 15;
    const int tgrp = tid >> 4;                   // timestep-in-superstep this thread stages
    const size_t row0 = (size_t)b * LL;

    ull state[8];
    #pragma unroll
    for (int j = 0; j < 8; ++j) state[j] = 0ull;

    auto issue = [&](int s) {
        if (s < NSUP) {
            const size_t row = row0 + (size_t)s * SS + tgrp;
            float* dstT = &ring[s & (DST - 1)][tgrp][0];
            const float* bhrow   = g_bh + (row * HH + h) * GN_ + n0;
            const float* convrow = g_xconv + row * DCONVCH;
            const float* xshrow  = g_xsh + row * PP;
            #pragma unroll
            for (int c = lane16; c < 40; c += 16) {
                const float* src;
                float* dst;
                if (c < 4)      { src = bhrow + c * 4;                           dst = dstT + c * 4; }
                else if (c < 8) { src = convrow + DIN + GN_ + n0 + (c - 4) * 4;  dst = dstT + 16 + (c - 4) * 4; }
                else            { src = xshrow + (c - 8) * 4;                    dst = dstT + 32 + (c - 8) * 4; }
                cp_async16(smem_u32(dst), src);
            }
            if (lane16 == 8) cp_async4(smem_u32(dstT + 160), g_dA + row * HH + h);
        }
        CP_COMMIT();
    };

    #pragma unroll
    for (int s = 0; s < DST - 1; ++s) issue(s);

    __half* yp = g_ypart + ((size_t)part * ROWS + row0) * DIN + (size_t)h * PP + tid;

    for (int s = 0; s < NSUP; ++s) {
        cp_wait<DST - 2>();        // stage s landed
        __syncthreads();           // visible to all warps; slot (s-1)%DST free for refill

        const float* slotp = &ring[s & (DST - 1)][0][0];
        #pragma unroll
        for (int i = 0; i < SS; ++i) {
            const float* s4 = slotp + i * SLOTF;
            const ull* s8 = (const ull*)s4;       // [0:8)=bh pairs, [8:16)=C pairs
            const float x = s4[32 + tid];
            const float dAv = s4[160];
            const ull dAp = f32x2_pack(dAv, dAv);
            const ull cfp = f32x2_pack(x, x);
            ull accA = 0ull, accB = 0ull;
            #pragma unroll
            for (int j = 0; j < 8; ++j) {
                state[j] = f32x2_fma(dAp, state[j], f32x2_mul(cfp, s8[j]));
                if (j & 1) accB = f32x2_fma(s8[8 + j], state[j], accB);
                else       accA = f32x2_fma(s8[8 + j], state[j], accA);
            }
            float2 a = f32x2_unpack(accA);
            float2 c = f32x2_unpack(accB);
            yp[(size_t)(s * SS + i) * DIN] = __float2half((a.x + a.y) + (c.x + c.y));
        }

        issue(s + DST - 1);        // refill slot (s-1)%DST
    }
}

// ---------------- 6) combine partials + D*x + gate + RMSNorm -> split bf16 (vectorized) ----------------
__global__ void combine_kernel(const float* __restrict__ D_param,
                               const float* __restrict__ rms_w) {
    const int row = blockIdx.x, tid = threadIdx.x;   // 256 threads, 4 contiguous c each
    __shared__ float red[256];
    const int c0 = tid * 4;

    float s0 = 0.f, s1 = 0.f, s2 = 0.f, s3 = 0.f;
    #pragma unroll
    for (int part = 0; part < NPART; ++part) {
        uint2 v = *(const uint2*)(g_ypart + ((size_t)part * ROWS + row) * DIN + c0);
        const __half2* hp = (const __half2*)&v;
        float2 f0 = __half22float2(hp[0]);
        float2 f1 = __half22float2(hp[1]);
        s0 += f0.x; s1 += f0.y; s2 += f1.x; s3 += f1.y;
    }
    const float Dh = D_param[c0 >> 7];
    const float4 xs = *(const float4*)(g_xsh + (size_t)row * PP + (c0 & 127));
    s0 = fmaf(Dh, xs.x, s0); s1 = fmaf(Dh, xs.y, s1);
    s2 = fmaf(Dh, xs.z, s2); s3 = fmaf(Dh, xs.w, s3);

    const float4 z = *(const float4*)(g_zx + (size_t)row * DPROJP + c0);
    float y0 = s0 * siluf(z.x), y1 = s1 * siluf(z.y);
    float y2 = s2 * siluf(z.z), y3 = s3 * siluf(z.w);

    red[tid] = y0 * y0 + y1 * y1 + y2 * y2 + y3 * y3;
    __syncthreads();
    #pragma unroll
    for (int s = 128; s > 0; s >>= 1) { if (tid < s) red[tid] += red[tid + s]; __syncthreads(); }
    const float rstd = rsqrtf(red[0] * (1.f / (float)DIN) + EPS_);

    const float4 rw = *(const float4*)(rms_w + c0);
    float v0 = y0 * rstd * rw.x, v1 = y1 * rstd * rw.y;
    float v2 = y2 * rstd * rw.z, v3 = y3 * rstd * rw.w;

    __nv_bfloat16 hv[4], lv[4];
    split_bf16(v0, hv[0], lv[0]); split_bf16(v1, hv[1], lv[1]);
    split_bf16(v2, hv[2], lv[2]); split_bf16(v3, hv[3], lv[3]);
    *(uint2*)(g_yh + (size_t)row * DIN + c0) = *(const uint2*)hv;
    *(uint2*)(g_yl + (size_t)row * DIN + c0) = *(const uint2*)lv;
}

// ---------------- launch ----------------
extern "C" void kernel_launch(void* const* d_in, const int* in_sizes, int n_in,
                              void* d_out, int out_size) {
    const float* u        = (const float*)d_in[0];
    const float* ln_gamma = (const float*)d_in[1];
    const float* ln_beta  = (const float*)d_in[2];
    const float* W_in     = (const float*)d_in[3];
    const float* conv_w   = (const float*)d_in[4];
    const float* conv_b   = (const float*)d_in[5];
    const float* dt_bias  = (const float*)d_in[6];
    const float* A_log    = (const float*)d_in[7];
    const float* D_param  = (const float*)d_in[8];
    const float* B_scale  = (const float*)d_in[9];
    const float* rms_w    = (const float*)d_in[10];
    const float* W_out    = (const float*)d_in[11];
    float* out = (float*)d_out;

    cudaFuncSetAttribute(mma_gemm_kernel<8>,
                         cudaFuncAttributeMaxDynamicSharedMemorySize, GEMM_SMEM);
    cudaFuncSetAttribute(mma_gemm_kernel<32>,
                         cudaFuncAttributeMaxDynamicSharedMemorySize, GEMM_SMEM);

    __nv_bfloat16 *p_xh, *p_xl, *p_winh, *p_winl, *p_wouth, *p_woutl, *p_yh, *p_yl;
    float* p_zx;
    cudaGetSymbolAddress((void**)&p_xh, g_xh);
    cudaGetSymbolAddress((void**)&p_xl, g_xl);
    cudaGetSymbolAddress((void**)&p_winh, g_WinT_h);
    cudaGetSymbolAddress((void**)&p_winl, g_WinT_l);
    cudaGetSymbolAddress((void**)&p_wouth, g_WoutT_h);
    cudaGetSymbolAddress((void**)&p_woutl, g_WoutT_l);
    cudaGetSymbolAddress((void**)&p_yh, g_yh);
    cudaGetSymbolAddress((void**)&p_yl, g_yl);
    cudaGetSymbolAddress((void**)&p_zx, g_zx);

    ln_kernel<<<ROWS, 256>>>(u, ln_gamma, ln_beta);
    transpose_win_kernel<<<dim3(DPROJP / 32, DM / 32), dim3(32, 8)>>>(W_in);
    transpose_wout_kernel<<<dim3(DM / 32, DIN / 32), dim3(32, 8)>>>(W_out);

    // GEMM1: zx[8192 x 2432(pad)] = xn @ W_in  (split-bf16 HMMA, 128x128 tile)
    mma_gemm_kernel<8><<<dim3(DPROJP / 128, ROWS / 128), 256, GEMM_SMEM>>>(
        p_xh, p_xl, p_winh, p_winl, p_zx, DPROJP, nullptr);

    conv_kernel<<<dim3(DCONVCH / 256, LL / CLT, BB), 256>>>(conv_w, conv_b);
    prep_kernel<<<ROWS, 128>>>(B_scale, dt_bias, A_log);

    scan_kernel<<<dim3(NPART, HH, BB), 128>>>();

    combine_kernel<<<ROWS, 256>>>(D_param, rms_w);

    // GEMM2: out[8192 x 256] = yg @ W_out + u
    mma_gemm_kernel<32><<<dim3(DM / 128, ROWS / 128), 256, GEMM_SMEM>>>(
        p_yh, p_yl, p_wouth, p_woutl, out, DM, u);
}

// round 10
// speedup vs baseline: 1.2736x; 1.0006x over previous
#include <cuda_runtime.h>
#include <cuda_bf16.h>
#include <cuda_fp16.h>
#include <math.h>
#include <stdint.h>

// ---------------- problem constants ----------------
#define BB 2
#define LL 4096
#define DM 256
#define DIN 1024          // D_INNER
#define GN_ 128           // NGROUPS*D_STATE
#define HH 8              // NHEADS
#define PP 128            // HEADDIM
#define DPROJ 2312        // D_IN_PROJ (logical)
#define DPROJP 2432       // padded to 19*128
#define DCONVCH 1280      // D_INNER + 2*GN
#define ROWS (BB*LL)      // 8192
#define EPS_ 1e-5f

#define NPART 8
#define NPN 16            // n per partition
#define SS 8              // scan superstep (timesteps per pipeline stage)
#define DST 4             // pipeline depth (stages)
#define NSUP (LL / SS)    // 512

// ---------------- scratch (static device allocations) ----------------
__device__ __align__(16) __nv_bfloat16 g_xh[(size_t)ROWS * DM];
__device__ __align__(16) __nv_bfloat16 g_xl[(size_t)ROWS * DM];
__device__ __align__(16) __nv_bfloat16 g_WinT_h[(size_t)DPROJP * DM];
__device__ __align__(16) __nv_bfloat16 g_WinT_l[(size_t)DPROJP * DM];
__device__ __align__(16) __nv_bfloat16 g_WoutT_h[(size_t)DM * DIN];
__device__ __align__(16) __nv_bfloat16 g_WoutT_l[(size_t)DM * DIN];
__device__ __align__(16) __nv_bfloat16 g_yh[(size_t)ROWS * DIN];
__device__ __align__(16) __nv_bfloat16 g_yl[(size_t)ROWS * DIN];
__device__ float g_zx[(size_t)ROWS * DPROJP];
__device__ float g_xconv[(size_t)ROWS * DCONVCH];
__device__ float g_dA[(size_t)ROWS * HH];
__device__ float g_xsh[(size_t)ROWS * PP];
__device__ float g_bh[(size_t)ROWS * HH * GN_];    // B*bscale*dt (33.5 MB)
__device__ __align__(16) __half g_ypart[(size_t)NPART * ROWS * DIN];   // fp16 partials (128 MB)

// ---------------- small helpers ----------------
__device__ __forceinline__ float siluf(float x) { return x / (1.f + expf(-x)); }

__device__ __forceinline__ void split_bf16(float v, __nv_bfloat16& h, __nv_bfloat16& l) {
    h = __float2bfloat16(v);
    l = __float2bfloat16(v - __bfloat162float(h));
}

typedef unsigned long long ull;
__device__ __forceinline__ ull f32x2_fma(ull a, ull b, ull c) {
    ull d; asm("fma.rn.f32x2 %0, %1, %2, %3;" : "=l"(d) : "l"(a), "l"(b), "l"(c)); return d;
}
__device__ __forceinline__ ull f32x2_mul(ull a, ull b) {
    ull d; asm("mul.rn.f32x2 %0, %1, %2;" : "=l"(d) : "l"(a), "l"(b)); return d;
}
__device__ __forceinline__ ull f32x2_pack(float lo, float hi) {
    ull d; asm("mov.b64 %0, {%1, %2};" : "=l"(d) : "f"(lo), "f"(hi)); return d;
}
__device__ __forceinline__ float2 f32x2_unpack(ull v) {
    float2 r; asm("mov.b64 {%0, %1}, %2;" : "=f"(r.x), "=f"(r.y) : "l"(v)); return r;
}

__device__ __forceinline__ uint32_t smem_u32(const void* p) {
    uint32_t a;
    asm("{ .reg .u64 t; cvta.to.shared.u64 t, %1; cvt.u32.u64 %0, t; }" : "=r"(a) : "l"(p));
    return a;
}

// ---------------- async copy helpers ----------------
__device__ __forceinline__ void cp_async16(uint32_t saddr, const void* gptr) {
    asm volatile("cp.async.cg.shared.global [%0], [%1], 16;"
                 :: "r"(saddr), "l"(gptr) : "memory");
}
__device__ __forceinline__ void cp_async4(uint32_t saddr, const void* gptr) {
    asm volatile("cp.async.ca.shared.global [%0], [%1], 4;"
                 :: "r"(saddr), "l"(gptr) : "memory");
}
#define CP_COMMIT() asm volatile("cp.async.commit_group;" ::: "memory")
template <int N> __device__ __forceinline__ void cp_wait() {
    asm volatile("cp.async.wait_group %0;" :: "n"(N) : "memory");
}

__device__ __forceinline__ void ldmatrix_x4(uint32_t* r, uint32_t addr) {
    asm volatile("ldmatrix.sync.aligned.m8n8.x4.shared.b16 {%0,%1,%2,%3}, [%4];"
                 : "=r"(r[0]), "=r"(r[1]), "=r"(r[2]), "=r"(r[3]) : "r"(addr));
}

__device__ __forceinline__ void mma_bf16(float* c, const uint32_t* a, uint32_t b0, uint32_t b1) {
    asm volatile(
        "mma.sync.aligned.m16n8k16.row.col.f32.bf16.bf16.f32 "
        "{%0,%1,%2,%3}, {%4,%5,%6,%7}, {%8,%9}, {%0,%1,%2,%3};"
        : "+f"(c[0]), "+f"(c[1]), "+f"(c[2]), "+f"(c[3])
        : "r"(a[0]), "r"(a[1]), "r"(a[2]), "r"(a[3]), "r"(b0), "r"(b1));
}

// ---------------- 1) LayerNorm -> split bf16 (single-pass, shuffle) ----------------
__global__ void ln_kernel(const float* __restrict__ u,
                          const float* __restrict__ gamma,
                          const float* __restrict__ beta) {
    __shared__ float w1[8], w2[8], bc[2];
    const int row = blockIdx.x, tid = threadIdx.x;
    const int wid = tid >> 5, lane = tid & 31;
    float v = u[(size_t)row * DM + tid];
    float s1 = v, s2 = v * v;
    #pragma unroll
    for (int o = 16; o > 0; o >>= 1) {
        s1 += __shfl_xor_sync(0xffffffffu, s1, o);
        s2 += __shfl_xor_sync(0xffffffffu, s2, o);
    }
    if (lane == 0) { w1[wid] = s1; w2[wid] = s2; }
    __syncthreads();
    if (wid == 0) {
        float a = (lane < 8) ? w1[lane] : 0.f;
        float b = (lane < 8) ? w2[lane] : 0.f;
        #pragma unroll
        for (int o = 4; o > 0; o >>= 1) {
            a += __shfl_xor_sync(0xffffffffu, a, o);
            b += __shfl_xor_sync(0xffffffffu, b, o);
        }
        if (lane == 0) {
            float mu = a * (1.f / 256.f);
            float var = b * (1.f / 256.f) - mu * mu;
            bc[0] = mu;
            bc[1] = rsqrtf(var + EPS_);
        }
    }
    __syncthreads();
    float xn = (v - bc[0]) * bc[1] * gamma[tid] + beta[tid];
    __nv_bfloat16 h, l;
    split_bf16(xn, h, l);
    g_xh[(size_t)row * DM + tid] = h;
    g_xl[(size_t)row * DM + tid] = l;
}

// ---------------- transposes + split of weights (tiled, coalesced) ----------------
__global__ void transpose_win_kernel(const float* __restrict__ W_in) {
    __shared__ float tile[32][33];
    const int tx = threadIdx.x, ty = threadIdx.y;        // 32 x 8
    const int n0 = blockIdx.x * 32, k0 = blockIdx.y * 32;
    #pragma unroll
    for (int dy = 0; dy < 32; dy += 8) {
        const int n = n0 + tx, k = k0 + ty + dy;
        tile[ty + dy][tx] = (n < DPROJ) ? W_in[(size_t)k * DPROJ + n] : 0.f;
    }
    __syncthreads();
    #pragma unroll
    for (int dy = 0; dy < 32; dy += 8) {
        const int n = n0 + ty + dy, k = k0 + tx;
        float v = tile[tx][ty + dy];
        __nv_bfloat16 h, l;
        split_bf16(v, h, l);
        g_WinT_h[(size_t)n * DM + k] = h;
        g_WinT_l[(size_t)n * DM + k] = l;
    }
}

__global__ void transpose_wout_kernel(const float* __restrict__ W_out) {
    __shared__ float tile[32][33];
    const int tx = threadIdx.x, ty = threadIdx.y;        // 32 x 8
    const int n0 = blockIdx.x * 32, k0 = blockIdx.y * 32;
    #pragma unroll
    for (int dy = 0; dy < 32; dy += 8) {
        tile[ty + dy][tx] = W_out[(size_t)(k0 + ty + dy) * DM + n0 + tx];
    }
    __syncthreads();
    #pragma unroll
    for (int dy = 0; dy < 32; dy += 8) {
        const int n = n0 + ty + dy, k = k0 + tx;
        float v = tile[tx][ty + dy];
        __nv_bfloat16 h, l;
        split_bf16(v, h, l);
        g_WoutT_h[(size_t)n * DIN + k] = h;
        g_WoutT_l[(size_t)n * DIN + k] = l;
    }
}

// ---------------- 2) split-bf16 GEMM, interleaved segments (Ah,Al,Bh,Bl per chunk) ----------------
// Per k-chunk of 32: stage all 4 operand tiles once, issue Ah*Bh + Al*Bh + Ah*Bl.
// Operand L2 traffic 256KB/CTA (was 384KB); 2-stage double buffer.
#define STR 40   // smem row stride (bf16): conflict-free for ldmatrix
#define OBUF (128 * STR * 2)          // bytes per operand buffer (10240)
#define STAGE4 (4 * OBUF)             // 40960
#define GEMM_SMEM (2 * STAGE4)        // 81920

template <int CPS>
__global__ void __launch_bounds__(256, 2)
mma_gemm_kernel(const __nv_bfloat16* __restrict__ Ah,
                const __nv_bfloat16* __restrict__ Al,
                const __nv_bfloat16* __restrict__ Bh,
                const __nv_bfloat16* __restrict__ Bl,
                float* __restrict__ C, int ldc,
                const float* __restrict__ Cadd) {
    constexpr int Kin = CPS * 32;
    extern __shared__ char dsmem[];
    const uint32_t sbase = smem_u32(dsmem);

    const int tid = threadIdx.x;
    const int wid = tid >> 5, lid = tid & 31;
    const int wm = wid >> 2;           // 0..1
    const int wn = wid & 3;            // 0..3
    const int tileRow = blockIdx.y * 128;
    const int tileCol = blockIdx.x * 128;

    // staging: threads 0-127 stage A-pair rows, 128-255 stage B-pair rows (64B each op)
    const int stRow = tid & 127;
    const bool stB = tid >= 128;
    const __nv_bfloat16* gH0 = stB ? Bh : Ah;
    const __nv_bfloat16* gL0 = stB ? Bl : Al;
    const size_t gRowOff = (size_t)((stB ? tileCol : tileRow) + stRow) * Kin;
    const uint32_t stSmemOff = (stB ? 2u * OBUF : 0u) + (uint32_t)(stRow * STR) * 2;

    const int aRowOff = (lid & 7) + ((lid >> 3) & 1) * 8;
    const int aKOff   = (lid >> 4) * 8;
    const int bNOff   = (lid & 7) + ((lid >> 4) & 1) * 8;
    const int bKOff   = ((lid >> 3) & 1) * 8;

    float acc[4][4][4];
    #pragma unroll
    for (int i = 0; i < 4; ++i)
        #pragma unroll
        for (int j = 0; j < 4; ++j)
            #pragma unroll
            for (int q = 0; q < 4; ++q) acc[i][j][q] = 0.f;

    auto issue = [&](int c) {
        if (c < CPS) {
            const __nv_bfloat16* gh = gH0 + gRowOff + c * 32;
            const __nv_bfloat16* gl = gL0 + gRowOff + c * 32;
            const uint32_t sh = sbase + (uint32_t)(c & 1) * STAGE4 + stSmemOff;
            const uint32_t sl = sh + OBUF;
            cp_async16(sh,      gh);
            cp_async16(sh + 16, gh + 8);
            cp_async16(sh + 32, gh + 16);
            cp_async16(sh + 48, gh + 24);
            cp_async16(sl,      gl);
            cp_async16(sl + 16, gl + 8);
            cp_async16(sl + 32, gl + 16);
            cp_async16(sl + 48, gl + 24);
        }
        CP_COMMIT();
    };

    issue(0);
    for (int c = 0; c < CPS; ++c) {
        cp_wait<0>();              // stage c landed (only group in flight)
        __syncthreads();           // all warps done with chunk c-1; stage c visible
        issue(c + 1);              // refill other buffer while computing c

        const uint32_t base = sbase + (uint32_t)(c & 1) * STAGE4;
        const uint32_t aHB = base;
        const uint32_t aLB = base + OBUF;
        const uint32_t bHB = base + 2u * OBUF;
        const uint32_t bLB = base + 3u * OBUF;

        #pragma unroll
        for (int kk2 = 0; kk2 < 2; ++kk2) {
            const int kk = kk2 * 16;
            uint32_t bh[2][4], bl[2][4];
            #pragma unroll
            for (int pr = 0; pr < 2; ++pr) {
                const uint32_t off = (uint32_t)((wn * 32 + pr * 16 + bNOff) * STR + kk + bKOff) * 2;
                ldmatrix_x4(bh[pr], bHB + off);
                ldmatrix_x4(bl[pr], bLB + off);
            }
            #pragma unroll
            for (int mt = 0; mt < 4; ++mt) {
                const uint32_t aoff = (uint32_t)((wm * 64 + mt * 16 + aRowOff) * STR + kk + aKOff) * 2;
                uint32_t ah[4];
                ldmatrix_x4(ah, aHB + aoff);
                #pragma unroll
                for (int nt = 0; nt < 4; ++nt) {
                    const int hi = (nt & 1) * 2;
                    mma_bf16(acc[mt][nt], ah, bh[nt >> 1][hi], bh[nt >> 1][hi + 1]);
                }
                #pragma unroll
                for (int nt = 0; nt < 4; ++nt) {
                    const int hi = (nt & 1) * 2;
                    mma_bf16(acc[mt][nt], ah, bl[nt >> 1][hi], bl[nt >> 1][hi + 1]);
                }
                uint32_t al[4];
                ldmatrix_x4(al, aLB + aoff);
                #pragma unroll
                for (int nt = 0; nt < 4; ++nt) {
                    const int hi = (nt & 1) * 2;
                    mma_bf16(acc[mt][nt], al, bh[nt >> 1][hi], bh[nt >> 1][hi + 1]);
                }
            }
        }
        __syncthreads();           // all warps done reading buf c before it's refilled at c+2
    }

    const int gID = lid >> 2, qid = lid & 3;
    #pragma unroll
    for (int mt = 0; mt < 4; ++mt) {
        const int r0 = tileRow + wm * 64 + mt * 16 + gID;
        #pragma unroll
        for (int nt = 0; nt < 4; ++nt) {
            const int col = tileCol + wn * 32 + nt * 8 + qid * 2;
            float2 v0 = make_float2(acc[mt][nt][0], acc[mt][nt][1]);
            float2 v1 = make_float2(acc[mt][nt][2], acc[mt][nt][3]);
            if (Cadd) {
                const float2 a0 = *(const float2*)(Cadd + (size_t)r0 * ldc + col);
                const float2 a1 = *(const float2*)(Cadd + (size_t)(r0 + 8) * ldc + col);
                v0.x += a0.x; v0.y += a0.y;
                v1.x += a1.x; v1.y += a1.y;
            }
            *(float2*)(C + (size_t)r0 * ldc + col) = v0;
            *(float2*)(C + (size_t)(r0 + 8) * ldc + col) = v1;
        }
    }
}

// ---------------- 3) causal depthwise conv (K=4) + SiLU, register ring over l ----------------
#define CLT 16
__global__ void conv_kernel(const float* __restrict__ conv_w,
                            const float* __restrict__ conv_b) {
    const int c = blockIdx.x * 256 + threadIdx.x;   // 0..1279 (grid.x = 5)
    const int l0 = blockIdx.y * CLT;
    const int b = blockIdx.z;
    const size_t base = ((size_t)b * LL) * DPROJP + DIN + c;
    const float w0 = conv_w[c * 4 + 0], w1 = conv_w[c * 4 + 1];
    const float w2 = conv_w[c * 4 + 2], w3 = conv_w[c * 4 + 3];
    const float bias = conv_b[c];

    float x0 = 0.f, x1 = 0.f, x2 = 0.f;
    if (l0 > 0) {
        x0 = g_zx[base + (size_t)(l0 - 3) * DPROJP];
        x1 = g_zx[base + (size_t)(l0 - 2) * DPROJP];
        x2 = g_zx[base + (size_t)(l0 - 1) * DPROJP];
    }
    #pragma unroll
    for (int i = 0; i < CLT; ++i) {
        const float x3 = g_zx[base + (size_t)(l0 + i) * DPROJP];
        float acc = fmaf(x0, w0, bias);
        acc = fmaf(x1, w1, acc);
        acc = fmaf(x2, w2, acc);
        acc = fmaf(x3, w3, acc);
        g_xconv[((size_t)b * LL + l0 + i) * DCONVCH + c] = siluf(acc);
        x0 = x1; x1 = x2; x2 = x3;
    }
}

// ---------------- 4) prep: dt/dA + x_shared mean + prescaled B (fused) ----------------
__global__ void prep_kernel(const float* __restrict__ Bscale,
                            const float* __restrict__ dt_bias,
                            const float* __restrict__ A_log) {
    __shared__ float sdt[HH];
    const int row = blockIdx.x, p = threadIdx.x;    // 128 threads
    if (p < HH) {
        float dt = g_zx[(size_t)row * DPROJP + 2304 + p] + dt_bias[p];
        float dtp = (dt > 20.f) ? dt : log1pf(expf(dt));
        sdt[p] = dtp;
        g_dA[row * HH + p] = expf(-expf(A_log[p]) * dtp);
    }
    const float* xrow = g_xconv + (size_t)row * DCONVCH;
    float s = 0.f;
    #pragma unroll
    for (int h = 0; h < HH; ++h) s += xrow[h * PP + p];
    g_xsh[(size_t)row * PP + p] = s * 0.125f;
    __syncthreads();
    const float Bn = xrow[DIN + p];                  // p == n here
    float* dst = g_bh + (size_t)row * (HH * GN_) + p;
    #pragma unroll
    for (int h = 0; h < HH; ++h)
        dst[h * GN_] = Bn * Bscale[h * GN_ + p] * sdt[h];
}

// ---------------- 5) selective scan: cp.async multistage pipeline ----------------
// Slot layout per timestep (168 floats): [0:16) bh (=B*bscale*dt), [16:32) C,
// [32:160) xsh, [160] dA, [161:168) pad.
#define SLOTF 168

__global__ void __launch_bounds__(128, 1)
scan_kernel() {
    __shared__ __align__(16) float ring[DST][SS][SLOTF];

    const int part = blockIdx.x, h = blockIdx.y, b = blockIdx.z;
    const int tid = threadIdx.x;                 // = p
    const int n0 = part * NPN;
    const int lane16 = tid & 15;
    const int tgrp = tid >> 4;                   // timestep-in-superstep this thread stages
    const size_t row0 = (size_t)b * LL;

    ull state[8];
    #pragma unroll
    for (int j = 0; j < 8; ++j) state[j] = 0ull;

    auto issue = [&](int s) {
        if (s < NSUP) {
            const size_t row = row0 + (size_t)s * SS + tgrp;
            float* dstT = &ring[s & (DST - 1)][tgrp][0];
            const float* bhrow   = g_bh + (row * HH + h) * GN_ + n0;
            const float* convrow = g_xconv + row * DCONVCH;
            const float* xshrow  = g_xsh + row * PP;
            #pragma unroll
            for (int c = lane16; c < 40; c += 16) {
                const float* src;
                float* dst;
                if (c < 4)      { src = bhrow + c * 4;                           dst = dstT + c * 4; }
                else if (c < 8) { src = convrow + DIN + GN_ + n0 + (c - 4) * 4;  dst = dstT + 16 + (c - 4) * 4; }
                else            { src = xshrow + (c - 8) * 4;                    dst = dstT + 32 + (c - 8) * 4; }
                cp_async16(smem_u32(dst), src);
            }
            if (lane16 == 8) cp_async4(smem_u32(dstT + 160), g_dA + row * HH + h);
        }
        CP_COMMIT();
    };

    #pragma unroll
    for (int s = 0; s < DST - 1; ++s) issue(s);

    __half* yp = g_ypart + ((size_t)part * ROWS + row0) * DIN + (size_t)h * PP + tid;

    for (int s = 0; s < NSUP; ++s) {
        cp_wait<DST - 2>();        // stage s landed
        __syncthreads();           // visible to all warps; slot (s-1)%DST free for refill

        const float* slotp = &ring[s & (DST - 1)][0][0];
        #pragma unroll
        for (int i = 0; i < SS; ++i) {
            const float* s4 = slotp + i * SLOTF;
            const ull* s8 = (const ull*)s4;       // [0:8)=bh pairs, [8:16)=C pairs
            const float x = s4[32 + tid];
            const float dAv = s4[160];
            const ull dAp = f32x2_pack(dAv, dAv);
            const ull cfp = f32x2_pack(x, x);
            ull accA = 0ull, accB = 0ull;
            #pragma unroll
            for (int j = 0; j < 8; ++j) {
                state[j] = f32x2_fma(dAp, state[j], f32x2_mul(cfp, s8[j]));
                if (j & 1) accB = f32x2_fma(s8[8 + j], state[j], accB);
                else       accA = f32x2_fma(s8[8 + j], state[j], accA);
            }
            float2 a = f32x2_unpack(accA);
            float2 c = f32x2_unpack(accB);
            yp[(size_t)(s * SS + i) * DIN] = __float2half((a.x + a.y) + (c.x + c.y));
        }

        issue(s + DST - 1);        // refill slot (s-1)%DST
    }
}

// ---------------- 6) combine partials + D*x + gate + RMSNorm -> split bf16 (vectorized) ----------------
__global__ void combine_kernel(const float* __restrict__ D_param,
                               const float* __restrict__ rms_w) {
    const int row = blockIdx.x, tid = threadIdx.x;   // 256 threads, 4 contiguous c each
    __shared__ float red[256];
    const int c0 = tid * 4;

    float s0 = 0.f, s1 = 0.f, s2 = 0.f, s3 = 0.f;
    #pragma unroll
    for (int part = 0; part < NPART; ++part) {
        uint2 v = *(const uint2*)(g_ypart + ((size_t)part * ROWS + row) * DIN + c0);
        const __half2* hp = (const __half2*)&v;
        float2 f0 = __half22float2(hp[0]);
        float2 f1 = __half22float2(hp[1]);
        s0 += f0.x; s1 += f0.y; s2 += f1.x; s3 += f1.y;
    }
    const float Dh = D_param[c0 >> 7];
    const float4 xs = *(const float4*)(g_xsh + (size_t)row * PP + (c0 & 127));
    s0 = fmaf(Dh, xs.x, s0); s1 = fmaf(Dh, xs.y, s1);
    s2 = fmaf(Dh, xs.z, s2); s3 = fmaf(Dh, xs.w, s3);

    const float4 z = *(const float4*)(g_zx + (size_t)row * DPROJP + c0);
    float y0 = s0 * siluf(z.x), y1 = s1 * siluf(z.y);
    float y2 = s2 * siluf(z.z), y3 = s3 * siluf(z.w);

    red[tid] = y0 * y0 + y1 * y1 + y2 * y2 + y3 * y3;
    __syncthreads();
    #pragma unroll
    for (int s = 128; s > 0; s >>= 1) { if (tid < s) red[tid] += red[tid + s]; __syncthreads(); }
    const float rstd = rsqrtf(red[0] * (1.f / (float)DIN) + EPS_);

    const float4 rw = *(const float4*)(rms_w + c0);
    float v0 = y0 * rstd * rw.x, v1 = y1 * rstd * rw.y;
    float v2 = y2 * rstd * rw.z, v3 = y3 * rstd * rw.w;

    __nv_bfloat16 hv[4], lv[4];
    split_bf16(v0, hv[0], lv[0]); split_bf16(v1, hv[1], lv[1]);
    split_bf16(v2, hv[2], lv[2]); split_bf16(v3, hv[3], lv[3]);
    *(uint2*)(g_yh + (size_t)row * DIN + c0) = *(const uint2*)hv;
    *(uint2*)(g_yl + (size_t)row * DIN + c0) = *(const uint2*)lv;
}

// ---------------- launch ----------------
extern "C" void kernel_launch(void* const* d_in, const int* in_sizes, int n_in,
                              void* d_out, int out_size) {
    const float* u        = (const float*)d_in[0];
    const float* ln_gamma = (const float*)d_in[1];
    const float* ln_beta  = (const float*)d_in[2];
    const float* W_in     = (const float*)d_in[3];
    const float* conv_w   = (const float*)d_in[4];
    const float* conv_b   = (const float*)d_in[5];
    const float* dt_bias  = (const float*)d_in[6];
    const float* A_log    = (const float*)d_in[7];
    const float* D_param  = (const float*)d_in[8];
    const float* B_scale  = (const float*)d_in[9];
    const float* rms_w    = (const float*)d_in[10];
    const float* W_out    = (const float*)d_in[11];
    float* out = (float*)d_out;

    cudaFuncSetAttribute(mma_gemm_kernel<8>,
                         cudaFuncAttributeMaxDynamicSharedMemorySize, GEMM_SMEM);
    cudaFuncSetAttribute(mma_gemm_kernel<32>,
                         cudaFuncAttributeMaxDynamicSharedMemorySize, GEMM_SMEM);

    __nv_bfloat16 *p_xh, *p_xl, *p_winh, *p_winl, *p_wouth, *p_woutl, *p_yh, *p_yl;
    float* p_zx;
    cudaGetSymbolAddress((void**)&p_xh, g_xh);
    cudaGetSymbolAddress((void**)&p_xl, g_xl);
    cudaGetSymbolAddress((void**)&p_winh, g_WinT_h);
    cudaGetSymbolAddress((void**)&p_winl, g_WinT_l);
    cudaGetSymbolAddress((void**)&p_wouth, g_WoutT_h);
    cudaGetSymbolAddress((void**)&p_woutl, g_WoutT_l);
    cudaGetSymbolAddress((void**)&p_yh, g_yh);
    cudaGetSymbolAddress((void**)&p_yl, g_yl);
    cudaGetSymbolAddress((void**)&p_zx, g_zx);

    ln_kernel<<<ROWS, 256>>>(u, ln_gamma, ln_beta);
    transpose_win_kernel<<<dim3(DPROJP / 32, DM / 32), dim3(32, 8)>>>(W_in);
    transpose_wout_kernel<<<dim3(DM / 32, DIN / 32), dim3(32, 8)>>>(W_out);

    // GEMM1: zx[8192 x 2432(pad)] = xn @ W_in  (split-bf16 HMMA, interleaved segments)
    mma_gemm_kernel<8><<<dim3(DPROJP / 128, ROWS / 128), 256, GEMM_SMEM>>>(
        p_xh, p_xl, p_winh, p_winl, p_zx, DPROJP, nullptr);

    conv_kernel<<<dim3(DCONVCH / 256, LL / CLT, BB), 256>>>(conv_w, conv_b);
    prep_kernel<<<ROWS, 128>>>(B_scale, dt_bias, A_log);

    scan_kernel<<<dim3(NPART, HH, BB), 128>>>();

    combine_kernel<<<ROWS, 256>>>(D_param, rms_w);

    // GEMM2: out[8192 x 256] = yg @ W_out + u
    mma_gemm_kernel<32><<<dim3(DM / 128, ROWS / 128), 256, GEMM_SMEM>>>(
        p_yh, p_yl, p_wouth, p_woutl, out, DM, u);
}

// round 11
// speedup vs baseline: 1.2779x; 1.0034x over previous
#include <cuda_runtime.h>
#include <cuda_bf16.h>
#include <cuda_fp16.h>
#include <math.h>
#include <stdint.h>

// ---------------- problem constants ----------------
#define BB 2
#define LL 4096
#define DM 256
#define DIN 1024          // D_INNER
#define GN_ 128           // NGROUPS*D_STATE
#define HH 8              // NHEADS
#define PP 128            // HEADDIM
#define DPROJ 2312        // D_IN_PROJ (logical)
#define DPROJP 2432       // padded to 19*128
#define DCONVCH 1280      // D_INNER + 2*GN
#define ROWS (BB*LL)      // 8192
#define EPS_ 1e-5f

#define NPART 8
#define NPN 16            // n per partition
#define SS 8              // scan superstep (timesteps per pipeline stage)
#define DST 4             // pipeline depth (stages)

// chunked scan
#define NCH 8
#define CLEN (LL / NCH)   // 512
#define NSUPC (CLEN / SS) // 64

// ---------------- scratch (static device allocations) ----------------
__device__ __align__(16) __nv_bfloat16 g_xh[(size_t)ROWS * DM];
__device__ __align__(16) __nv_bfloat16 g_xl[(size_t)ROWS * DM];
__device__ __align__(16) __nv_bfloat16 g_WinT_h[(size_t)DPROJP * DM];
__device__ __align__(16) __nv_bfloat16 g_WinT_l[(size_t)DPROJP * DM];
__device__ __align__(16) __nv_bfloat16 g_WoutT_h[(size_t)DM * DIN];
__device__ __align__(16) __nv_bfloat16 g_WoutT_l[(size_t)DM * DIN];
__device__ __align__(16) __nv_bfloat16 g_yh[(size_t)ROWS * DIN];
__device__ __align__(16) __nv_bfloat16 g_yl[(size_t)ROWS * DIN];
__device__ float g_zx[(size_t)ROWS * DPROJP];
__device__ float g_xconv[(size_t)ROWS * DCONVCH];
__device__ float g_dA[(size_t)ROWS * HH];
__device__ float g_xsh[(size_t)ROWS * PP];
__device__ float g_bh[(size_t)ROWS * HH * GN_];    // B*bscale*dt (33.5 MB)
__device__ __align__(16) __half g_ypart[(size_t)NPART * ROWS * DIN];   // fp16 partials (128 MB)

typedef unsigned long long ull;
// chunk boundary states: lin = ((ch*NPART+part)*HH+h)*BB+b, ch in 0..NCH-2
__device__ __align__(16) ull g_sf[(NCH - 1) * NPART * HH * BB][8][128];   // 7.3 MB
__device__ float g_aprod[(NCH - 1) * NPART * HH * BB];

// ---------------- small helpers ----------------
__device__ __forceinline__ float siluf(float x) { return x / (1.f + expf(-x)); }

__device__ __forceinline__ void split_bf16(float v, __nv_bfloat16& h, __nv_bfloat16& l) {
    h = __float2bfloat16(v);
    l = __float2bfloat16(v - __bfloat162float(h));
}

__device__ __forceinline__ ull f32x2_fma(ull a, ull b, ull c) {
    ull d; asm("fma.rn.f32x2 %0, %1, %2, %3;" : "=l"(d) : "l"(a), "l"(b), "l"(c)); return d;
}
__device__ __forceinline__ ull f32x2_mul(ull a, ull b) {
    ull d; asm("mul.rn.f32x2 %0, %1, %2;" : "=l"(d) : "l"(a), "l"(b)); return d;
}
__device__ __forceinline__ ull f32x2_pack(float lo, float hi) {
    ull d; asm("mov.b64 %0, {%1, %2};" : "=l"(d) : "f"(lo), "f"(hi)); return d;
}
__device__ __forceinline__ float2 f32x2_unpack(ull v) {
    float2 r; asm("mov.b64 {%0, %1}, %2;" : "=f"(r.x), "=f"(r.y) : "l"(v)); return r;
}

__device__ __forceinline__ uint32_t smem_u32(const void* p) {
    uint32_t a;
    asm("{ .reg .u64 t; cvta.to.shared.u64 t, %1; cvt.u32.u64 %0, t; }" : "=r"(a) : "l"(p));
    return a;
}

// ---------------- async copy helpers ----------------
__device__ __forceinline__ void cp_async16(uint32_t saddr, const void* gptr) {
    asm volatile("cp.async.cg.shared.global [%0], [%1], 16;"
                 :: "r"(saddr), "l"(gptr) : "memory");
}
__device__ __forceinline__ void cp_async4(uint32_t saddr, const void* gptr) {
    asm volatile("cp.async.ca.shared.global [%0], [%1], 4;"
                 :: "r"(saddr), "l"(gptr) : "memory");
}
#define CP_COMMIT() asm volatile("cp.async.commit_group;" ::: "memory")
template <int N> __device__ __forceinline__ void cp_wait() {
    asm volatile("cp.async.wait_group %0;" :: "n"(N) : "memory");
}

__device__ __forceinline__ void ldmatrix_x4(uint32_t* r, uint32_t addr) {
    asm volatile("ldmatrix.sync.aligned.m8n8.x4.shared.b16 {%0,%1,%2,%3}, [%4];"
                 : "=r"(r[0]), "=r"(r[1]), "=r"(r[2]), "=r"(r[3]) : "r"(addr));
}

__device__ __forceinline__ void mma_bf16(float* c, const uint32_t* a, uint32_t b0, uint32_t b1) {
    asm volatile(
        "mma.sync.aligned.m16n8k16.row.col.f32.bf16.bf16.f32 "
        "{%0,%1,%2,%3}, {%4,%5,%6,%7}, {%8,%9}, {%0,%1,%2,%3};"
        : "+f"(c[0]), "+f"(c[1]), "+f"(c[2]), "+f"(c[3])
        : "r"(a[0]), "r"(a[1]), "r"(a[2]), "r"(a[3]), "r"(b0), "r"(b1));
}

// ---------------- 1) LayerNorm -> split bf16 (single-pass, shuffle) ----------------
__global__ void ln_kernel(const float* __restrict__ u,
                          const float* __restrict__ gamma,
                          const float* __restrict__ beta) {
    __shared__ float w1[8], w2[8], bc[2];
    const int row = blockIdx.x, tid = threadIdx.x;
    const int wid = tid >> 5, lane = tid & 31;
    float v = u[(size_t)row * DM + tid];
    float s1 = v, s2 = v * v;
    #pragma unroll
    for (int o = 16; o > 0; o >>= 1) {
        s1 += __shfl_xor_sync(0xffffffffu, s1, o);
        s2 += __shfl_xor_sync(0xffffffffu, s2, o);
    }
    if (lane == 0) { w1[wid] = s1; w2[wid] = s2; }
    __syncthreads();
    if (wid == 0) {
        float a = (lane < 8) ? w1[lane] : 0.f;
        float b = (lane < 8) ? w2[lane] : 0.f;
        #pragma unroll
        for (int o = 4; o > 0; o >>= 1) {
            a += __shfl_xor_sync(0xffffffffu, a, o);
            b += __shfl_xor_sync(0xffffffffu, b, o);
        }
        if (lane == 0) {
            float mu = a * (1.f / 256.f);
            float var = b * (1.f / 256.f) - mu * mu;
            bc[0] = mu;
            bc[1] = rsqrtf(var + EPS_);
        }
    }
    __syncthreads();
    float xn = (v - bc[0]) * bc[1] * gamma[tid] + beta[tid];
    __nv_bfloat16 h, l;
    split_bf16(xn, h, l);
    g_xh[(size_t)row * DM + tid] = h;
    g_xl[(size_t)row * DM + tid] = l;
}

// ---------------- transposes + split of weights (tiled, coalesced) ----------------
__global__ void transpose_win_kernel(const float* __restrict__ W_in) {
    __shared__ float tile[32][33];
    const int tx = threadIdx.x, ty = threadIdx.y;        // 32 x 8
    const int n0 = blockIdx.x * 32, k0 = blockIdx.y * 32;
    #pragma unroll
    for (int dy = 0; dy < 32; dy += 8) {
        const int n = n0 + tx, k = k0 + ty + dy;
        tile[ty + dy][tx] = (n < DPROJ) ? W_in[(size_t)k * DPROJ + n] : 0.f;
    }
    __syncthreads();
    #pragma unroll
    for (int dy = 0; dy < 32; dy += 8) {
        const int n = n0 + ty + dy, k = k0 + tx;
        float v = tile[tx][ty + dy];
        __nv_bfloat16 h, l;
        split_bf16(v, h, l);
        g_WinT_h[(size_t)n * DM + k] = h;
        g_WinT_l[(size_t)n * DM + k] = l;
    }
}

__global__ void transpose_wout_kernel(const float* __restrict__ W_out) {
    __shared__ float tile[32][33];
    const int tx = threadIdx.x, ty = threadIdx.y;        // 32 x 8
    const int n0 = blockIdx.x * 32, k0 = blockIdx.y * 32;
    #pragma unroll
    for (int dy = 0; dy < 32; dy += 8) {
        tile[ty + dy][tx] = W_out[(size_t)(k0 + ty + dy) * DM + n0 + tx];
    }
    __syncthreads();
    #pragma unroll
    for (int dy = 0; dy < 32; dy += 8) {
        const int n = n0 + ty + dy, k = k0 + tx;
        float v = tile[tx][ty + dy];
        __nv_bfloat16 h, l;
        split_bf16(v, h, l);
        g_WoutT_h[(size_t)n * DIN + k] = h;
        g_WoutT_l[(size_t)n * DIN + k] = l;
    }
}

// ---------------- 2) split-bf16 GEMM, interleaved segments (Ah,Al,Bh,Bl per chunk) ----------------
#define STR 40   // smem row stride (bf16): conflict-free for ldmatrix
#define OBUF (128 * STR * 2)          // bytes per operand buffer (10240)
#define STAGE4 (4 * OBUF)             // 40960
#define GEMM_SMEM (2 * STAGE4)        // 81920

template <int CPS>
__global__ void __launch_bounds__(256, 2)
mma_gemm_kernel(const __nv_bfloat16* __restrict__ Ah,
                const __nv_bfloat16* __restrict__ Al,
                const __nv_bfloat16* __restrict__ Bh,
                const __nv_bfloat16* __restrict__ Bl,
                float* __restrict__ C, int ldc,
                const float* __restrict__ Cadd) {
    constexpr int Kin = CPS * 32;
    extern __shared__ char dsmem[];
    const uint32_t sbase = smem_u32(dsmem);

    const int tid = threadIdx.x;
    const int wid = tid >> 5, lid = tid & 31;
    const int wm = wid >> 2;           // 0..1
    const int wn = wid & 3;            // 0..3
    const int tileRow = blockIdx.y * 128;
    const int tileCol = blockIdx.x * 128;

    const int stRow = tid & 127;
    const bool stB = tid >= 128;
    const __nv_bfloat16* gH0 = stB ? Bh : Ah;
    const __nv_bfloat16* gL0 = stB ? Bl : Al;
    const size_t gRowOff = (size_t)((stB ? tileCol : tileRow) + stRow) * Kin;
    const uint32_t stSmemOff = (stB ? 2u * OBUF : 0u) + (uint32_t)(stRow * STR) * 2;

    const int aRowOff = (lid & 7) + ((lid >> 3) & 1) * 8;
    const int aKOff   = (lid >> 4) * 8;
    const int bNOff   = (lid & 7) + ((lid >> 4) & 1) * 8;
    const int bKOff   = ((lid >> 3) & 1) * 8;

    float acc[4][4][4];
    #pragma unroll
    for (int i = 0; i < 4; ++i)
        #pragma unroll
        for (int j = 0; j < 4; ++j)
            #pragma unroll
            for (int q = 0; q < 4; ++q) acc[i][j][q] = 0.f;

    auto issue = [&](int c) {
        if (c < CPS) {
            const __nv_bfloat16* gh = gH0 + gRowOff + c * 32;
            const __nv_bfloat16* gl = gL0 + gRowOff + c * 32;
            const uint32_t sh = sbase + (uint32_t)(c & 1) * STAGE4 + stSmemOff;
            const uint32_t sl = sh + OBUF;
            cp_async16(sh,      gh);
            cp_async16(sh + 16, gh + 8);
            cp_async16(sh + 32, gh + 16);
            cp_async16(sh + 48, gh + 24);
            cp_async16(sl,      gl);
            cp_async16(sl + 16, gl + 8);
            cp_async16(sl + 32, gl + 16);
            cp_async16(sl + 48, gl + 24);
        }
        CP_COMMIT();
    };

    issue(0);
    for (int c = 0; c < CPS; ++c) {
        cp_wait<0>();
        __syncthreads();
        issue(c + 1);

        const uint32_t base = sbase + (uint32_t)(c & 1) * STAGE4;
        const uint32_t aHB = base;
        const uint32_t aLB = base + OBUF;
        const uint32_t bHB = base + 2u * OBUF;
        const uint32_t bLB = base + 3u * OBUF;

        #pragma unroll
        for (int kk2 = 0; kk2 < 2; ++kk2) {
            const int kk = kk2 * 16;
            uint32_t bh[2][4], bl[2][4];
            #pragma unroll
            for (int pr = 0; pr < 2; ++pr) {
                const uint32_t off = (uint32_t)((wn * 32 + pr * 16 + bNOff) * STR + kk + bKOff) * 2;
                ldmatrix_x4(bh[pr], bHB + off);
                ldmatrix_x4(bl[pr], bLB + off);
            }
            #pragma unroll
            for (int mt = 0; mt < 4; ++mt) {
                const uint32_t aoff = (uint32_t)((wm * 64 + mt * 16 + aRowOff) * STR + kk + aKOff) * 2;
                uint32_t ah[4];
                ldmatrix_x4(ah, aHB + aoff);
                #pragma unroll
                for (int nt = 0; nt < 4; ++nt) {
                    const int hi = (nt & 1) * 2;
                    mma_bf16(acc[mt][nt], ah, bh[nt >> 1][hi], bh[nt >> 1][hi + 1]);
                }
                #pragma unroll
                for (int nt = 0; nt < 4; ++nt) {
                    const int hi = (nt & 1) * 2;
                    mma_bf16(acc[mt][nt], ah, bl[nt >> 1][hi], bl[nt >> 1][hi + 1]);
                }
                uint32_t al[4];
                ldmatrix_x4(al, aLB + aoff);
                #pragma unroll
                for (int nt = 0; nt < 4; ++nt) {
                    const int hi = (nt & 1) * 2;
                    mma_bf16(acc[mt][nt], al, bh[nt >> 1][hi], bh[nt >> 1][hi + 1]);
                }
            }
        }
        __syncthreads();
    }

    const int gID = lid >> 2, qid = lid & 3;
    #pragma unroll
    for (int mt = 0; mt < 4; ++mt) {
        const int r0 = tileRow + wm * 64 + mt * 16 + gID;
        #pragma unroll
        for (int nt = 0; nt < 4; ++nt) {
            const int col = tileCol + wn * 32 + nt * 8 + qid * 2;
            float2 v0 = make_float2(acc[mt][nt][0], acc[mt][nt][1]);
            float2 v1 = make_float2(acc[mt][nt][2], acc[mt][nt][3]);
            if (Cadd) {
                const float2 a0 = *(const float2*)(Cadd + (size_t)r0 * ldc + col);
                const float2 a1 = *(const float2*)(Cadd + (size_t)(r0 + 8) * ldc + col);
                v0.x += a0.x; v0.y += a0.y;
                v1.x += a1.x; v1.y += a1.y;
            }
            *(float2*)(C + (size_t)r0 * ldc + col) = v0;
            *(float2*)(C + (size_t)(r0 + 8) * ldc + col) = v1;
        }
    }
}

// ---------------- 3) causal depthwise conv (K=4) + SiLU, register ring over l ----------------
#define CLT 16
__global__ void conv_kernel(const float* __restrict__ conv_w,
                            const float* __restrict__ conv_b) {
    const int c = blockIdx.x * 256 + threadIdx.x;   // 0..1279 (grid.x = 5)
    const int l0 = blockIdx.y * CLT;
    const int b = blockIdx.z;
    const size_t base = ((size_t)b * LL) * DPROJP + DIN + c;
    const float w0 = conv_w[c * 4 + 0], w1 = conv_w[c * 4 + 1];
    const float w2 = conv_w[c * 4 + 2], w3 = conv_w[c * 4 + 3];
    const float bias = conv_b[c];

    float x0 = 0.f, x1 = 0.f, x2 = 0.f;
    if (l0 > 0) {
        x0 = g_zx[base + (size_t)(l0 - 3) * DPROJP];
        x1 = g_zx[base + (size_t)(l0 - 2) * DPROJP];
        x2 = g_zx[base + (size_t)(l0 - 1) * DPROJP];
    }
    #pragma unroll
    for (int i = 0; i < CLT; ++i) {
        const float x3 = g_zx[base + (size_t)(l0 + i) * DPROJP];
        float acc = fmaf(x0, w0, bias);
        acc = fmaf(x1, w1, acc);
        acc = fmaf(x2, w2, acc);
        acc = fmaf(x3, w3, acc);
        g_xconv[((size_t)b * LL + l0 + i) * DCONVCH + c] = siluf(acc);
        x0 = x1; x1 = x2; x2 = x3;
    }
}

// ---------------- 4) prep: dt/dA + x_shared mean + prescaled B (fused) ----------------
__global__ void prep_kernel(const float* __restrict__ Bscale,
                            const float* __restrict__ dt_bias,
                            const float* __restrict__ A_log) {
    __shared__ float sdt[HH];
    const int row = blockIdx.x, p = threadIdx.x;    // 128 threads
    if (p < HH) {
        float dt = g_zx[(size_t)row * DPROJP + 2304 + p] + dt_bias[p];
        float dtp = (dt > 20.f) ? dt : log1pf(expf(dt));
        sdt[p] = dtp;
        g_dA[row * HH + p] = expf(-expf(A_log[p]) * dtp);
    }
    const float* xrow = g_xconv + (size_t)row * DCONVCH;
    float s = 0.f;
    #pragma unroll
    for (int h = 0; h < HH; ++h) s += xrow[h * PP + p];
    g_xsh[(size_t)row * PP + p] = s * 0.125f;
    __syncthreads();
    const float Bn = xrow[DIN + p];                  // p == n here
    float* dst = g_bh + (size_t)row * (HH * GN_) + p;
    #pragma unroll
    for (int h = 0; h < HH; ++h)
        dst[h * GN_] = Bn * Bscale[h * GN_ + p] * sdt[h];
}

// ---------------- 5a) chunked scan pass 1: state-only per chunk (chunks 0..NCH-2) ----------------
// slot: [0:16) bh, [16:144) xsh, [144] dA, pad to 152
#define SLOT1 152

__global__ void __launch_bounds__(128, 1)
scan_state_kernel() {
    __shared__ __align__(16) float ring[DST][SS][SLOT1];

    const int part = blockIdx.x, h = blockIdx.y;
    const int b = blockIdx.z % BB, ch = blockIdx.z / BB;   // ch in 0..NCH-2
    const int tid = threadIdx.x;                 // = p
    const int n0 = part * NPN;
    const int lane16 = tid & 15;
    const int tgrp = tid >> 4;
    const size_t row0 = (size_t)b * LL + (size_t)ch * CLEN;

    ull state[8];
    #pragma unroll
    for (int j = 0; j < 8; ++j) state[j] = 0ull;

    auto issue = [&](int s) {
        if (s < NSUPC) {
            const size_t row = row0 + (size_t)s * SS + tgrp;
            float* dstT = &ring[s & (DST - 1)][tgrp][0];
            const float* bhrow  = g_bh + (row * HH + h) * GN_ + n0;
            const float* xshrow = g_xsh + row * PP;
            #pragma unroll
            for (int c = lane16; c < 36; c += 16) {
                const float* src;
                float* dst;
                if (c < 4) { src = bhrow + c * 4;        dst = dstT + c * 4; }
                else       { src = xshrow + (c - 4) * 4; dst = dstT + 16 + (c - 4) * 4; }
                cp_async16(smem_u32(dst), src);
            }
            if (lane16 == 8) cp_async4(smem_u32(dstT + 144), g_dA + row * HH + h);
        }
        CP_COMMIT();
    };

    #pragma unroll
    for (int s = 0; s < DST - 1; ++s) issue(s);

    float ap = 1.f;
    for (int s = 0; s < NSUPC; ++s) {
        cp_wait<DST - 2>();
        __syncthreads();

        const float* slotp = &ring[s & (DST - 1)][0][0];
        #pragma unroll
        for (int i = 0; i < SS; ++i) {
            const float* s4 = slotp + i * SLOT1;
            const ull* s8 = (const ull*)s4;       // [0:8) = bh pairs
            const float x = s4[16 + tid];
            const float dAv = s4[144];
            const ull dAp = f32x2_pack(dAv, dAv);
            const ull cfp = f32x2_pack(x, x);
            #pragma unroll
            for (int j = 0; j < 8; ++j)
                state[j] = f32x2_fma(dAp, state[j], f32x2_mul(cfp, s8[j]));
            ap *= dAv;
        }
        issue(s + DST - 1);
    }

    const int lin = ((ch * NPART + part) * HH + h) * BB + b;
    #pragma unroll
    for (int j = 0; j < 8; ++j) g_sf[lin][j][tid] = state[j];
    if (tid == 0) g_aprod[lin] = ap;
}

// ---------------- 5b) chunked scan pass 2: full scan per chunk with combined init ----------------
// Slot layout per timestep (168 floats): [0:16) bh, [16:32) C, [32:160) xsh, [160] dA.
#define SLOTF 168

__global__ void __launch_bounds__(128, 1)
scan_y_kernel() {
    __shared__ __align__(16) float ring[DST][SS][SLOTF];

    const int part = blockIdx.x, h = blockIdx.y;
    const int b = blockIdx.z % BB, ch = blockIdx.z / BB;   // ch in 0..NCH-1
    const int tid = threadIdx.x;                 // = p
    const int n0 = part * NPN;
    const int lane16 = tid & 15;
    const int tgrp = tid >> 4;
    const size_t row0 = (size_t)b * LL + (size_t)ch * CLEN;

    // init state = sum over prior chunks
    ull state[8];
    #pragma unroll
    for (int j = 0; j < 8; ++j) state[j] = 0ull;
    if (ch > 0) {
        float w = 1.f;
        for (int k = ch - 1; k >= 0; --k) {
            const int lin = ((k * NPART + part) * HH + h) * BB + b;
            const ull wp = f32x2_pack(w, w);
            #pragma unroll
            for (int j = 0; j < 8; ++j)
                state[j] = f32x2_fma(wp, g_sf[lin][j][tid], state[j]);
            w *= g_aprod[lin];
        }
    }

    auto issue = [&](int s) {
        if (s < NSUPC) {
            const size_t row = row0 + (size_t)s * SS + tgrp;
            float* dstT = &ring[s & (DST - 1)][tgrp][0];
            const float* bhrow   = g_bh + (row * HH + h) * GN_ + n0;
            const float* convrow = g_xconv + row * DCONVCH;
            const float* xshrow  = g_xsh + row * PP;
            #pragma unroll
            for (int c = lane16; c < 40; c += 16) {
                const float* src;
                float* dst;
                if (c < 4)      { src = bhrow + c * 4;                           dst = dstT + c * 4; }
                else if (c < 8) { src = convrow + DIN + GN_ + n0 + (c - 4) * 4;  dst = dstT + 16 + (c - 4) * 4; }
                else            { src = xshrow + (c - 8) * 4;                    dst = dstT + 32 + (c - 8) * 4; }
                cp_async16(smem_u32(dst), src);
            }
            if (lane16 == 8) cp_async4(smem_u32(dstT + 160), g_dA + row * HH + h);
        }
        CP_COMMIT();
    };

    #pragma unroll
    for (int s = 0; s < DST - 1; ++s) issue(s);

    __half* yp = g_ypart + ((size_t)part * ROWS + row0) * DIN + (size_t)h * PP + tid;

    for (int s = 0; s < NSUPC; ++s) {
        cp_wait<DST - 2>();
        __syncthreads();

        const float* slotp = &ring[s & (DST - 1)][0][0];
        #pragma unroll
        for (int i = 0; i < SS; ++i) {
            const float* s4 = slotp + i * SLOTF;
            const ull* s8 = (const ull*)s4;       // [0:8)=bh pairs, [8:16)=C pairs
            const float x = s4[32 + tid];
            const float dAv = s4[160];
            const ull dAp = f32x2_pack(dAv, dAv);
            const ull cfp = f32x2_pack(x, x);
            ull accA = 0ull, accB = 0ull;
            #pragma unroll
            for (int j = 0; j < 8; ++j) {
                state[j] = f32x2_fma(dAp, state[j], f32x2_mul(cfp, s8[j]));
                if (j & 1) accB = f32x2_fma(s8[8 + j], state[j], accB);
                else       accA = f32x2_fma(s8[8 + j], state[j], accA);
            }
            float2 a = f32x2_unpack(accA);
            float2 c = f32x2_unpack(accB);
            yp[(size_t)(s * SS + i) * DIN] = __float2half((a.x + a.y) + (c.x + c.y));
        }
        issue(s + DST - 1);
    }
}

// ---------------- 6) combine partials + D*x + gate + RMSNorm -> split bf16 (vectorized) ----------------
__global__ void combine_kernel(const float* __restrict__ D_param,
                               const float* __restrict__ rms_w) {
    const int row = blockIdx.x, tid = threadIdx.x;   // 256 threads, 4 contiguous c each
    __shared__ float red[256];
    const int c0 = tid * 4;

    float s0 = 0.f, s1 = 0.f, s2 = 0.f, s3 = 0.f;
    #pragma unroll
    for (int part = 0; part < NPART; ++part) {
        uint2 v = *(const uint2*)(g_ypart + ((size_t)part * ROWS + row) * DIN + c0);
        const __half2* hp = (const __half2*)&v;
        float2 f0 = __half22float2(hp[0]);
        float2 f1 = __half22float2(hp[1]);
        s0 += f0.x; s1 += f0.y; s2 += f1.x; s3 += f1.y;
    }
    const float Dh = D_param[c0 >> 7];
    const float4 xs = *(const float4*)(g_xsh + (size_t)row * PP + (c0 & 127));
    s0 = fmaf(Dh, xs.x, s0); s1 = fmaf(Dh, xs.y, s1);
    s2 = fmaf(Dh, xs.z, s2); s3 = fmaf(Dh, xs.w, s3);

    const float4 z = *(const float4*)(g_zx + (size_t)row * DPROJP + c0);
    float y0 = s0 * siluf(z.x), y1 = s1 * siluf(z.y);
    float y2 = s2 * siluf(z.z), y3 = s3 * siluf(z.w);

    red[tid] = y0 * y0 + y1 * y1 + y2 * y2 + y3 * y3;
    __syncthreads();
    #pragma unroll
    for (int s = 128; s > 0; s >>= 1) { if (tid < s) red[tid] += red[tid + s]; __syncthreads(); }
    const float rstd = rsqrtf(red[0] * (1.f / (float)DIN) + EPS_);

    const float4 rw = *(const float4*)(rms_w + c0);
    float v0 = y0 * rstd * rw.x, v1 = y1 * rstd * rw.y;
    float v2 = y2 * rstd * rw.z, v3 = y3 * rstd * rw.w;

    __nv_bfloat16 hv[4], lv[4];
    split_bf16(v0, hv[0], lv[0]); split_bf16(v1, hv[1], lv[1]);
    split_bf16(v2, hv[2], lv[2]); split_bf16(v3, hv[3], lv[3]);
    *(uint2*)(g_yh + (size_t)row * DIN + c0) = *(const uint2*)hv;
    *(uint2*)(g_yl + (size_t)row * DIN + c0) = *(const uint2*)lv;
}

// ---------------- launch ----------------
extern "C" void kernel_launch(void* const* d_in, const int* in_sizes, int n_in,
                              void* d_out, int out_size) {
    const float* u        = (const float*)d_in[0];
    const float* ln_gamma = (const float*)d_in[1];
    const float* ln_beta  = (const float*)d_in[2];
    const float* W_in     = (const float*)d_in[3];
    const float* conv_w   = (const float*)d_in[4];
    const float* conv_b   = (const float*)d_in[5];
    const float* dt_bias  = (const float*)d_in[6];
    const float* A_log    = (const float*)d_in[7];
    const float* D_param  = (const float*)d_in[8];
    const float* B_scale  = (const float*)d_in[9];
    const float* rms_w    = (const float*)d_in[10];
    const float* W_out    = (const float*)d_in[11];
    float* out = (float*)d_out;

    cudaFuncSetAttribute(mma_gemm_kernel<8>,
                         cudaFuncAttributeMaxDynamicSharedMemorySize, GEMM_SMEM);
    cudaFuncSetAttribute(mma_gemm_kernel<32>,
                         cudaFuncAttributeMaxDynamicSharedMemorySize, GEMM_SMEM);

    __nv_bfloat16 *p_xh, *p_xl, *p_winh, *p_winl, *p_wouth, *p_woutl, *p_yh, *p_yl;
    float* p_zx;
    cudaGetSymbolAddress((void**)&p_xh, g_xh);
    cudaGetSymbolAddress((void**)&p_xl, g_xl);
    cudaGetSymbolAddress((void**)&p_winh, g_WinT_h);
    cudaGetSymbolAddress((void**)&p_winl, g_WinT_l);
    cudaGetSymbolAddress((void**)&p_wouth, g_WoutT_h);
    cudaGetSymbolAddress((void**)&p_woutl, g_WoutT_l);
    cudaGetSymbolAddress((void**)&p_yh, g_yh);
    cudaGetSymbolAddress((void**)&p_yl, g_yl);
    cudaGetSymbolAddress((void**)&p_zx, g_zx);

    ln_kernel<<<ROWS, 256>>>(u, ln_gamma, ln_beta);
    transpose_win_kernel<<<dim3(DPROJP / 32, DM / 32), dim3(32, 8)>>>(W_in);
    transpose_wout_kernel<<<dim3(DM / 32, DIN / 32), dim3(32, 8)>>>(W_out);

    // GEMM1: zx[8192 x 2432(pad)] = xn @ W_in  (split-bf16 HMMA, interleaved segments)
    mma_gemm_kernel<8><<<dim3(DPROJP / 128, ROWS / 128), 256, GEMM_SMEM>>>(
        p_xh, p_xl, p_winh, p_winl, p_zx, DPROJP, nullptr);

    conv_kernel<<<dim3(DCONVCH / 256, LL / CLT, BB), 256>>>(conv_w, conv_b);
    prep_kernel<<<ROWS, 128>>>(B_scale, dt_bias, A_log);

    // chunked scan: pass 1 (state-only, chunks 0..NCH-2), pass 2 (full, all chunks)
    scan_state_kernel<<<dim3(NPART, HH, BB * (NCH - 1)), 128>>>();
    scan_y_kernel<<<dim3(NPART, HH, BB * NCH), 128>>>();

    combine_kernel<<<ROWS, 256>>>(D_param, rms_w);

    // GEMM2: out[8192 x 256] = yg @ W_out + u
    mma_gemm_kernel<32><<<dim3(DM / 128, ROWS / 128), 256, GEMM_SMEM>>>(
        p_yh, p_yl, p_wouth, p_woutl, out, DM, u);
}